// round 11
// baseline (speedup 1.0000x reference)
#include <cuda_runtime.h>
#include <cuda_bf16.h>
#include <stdint.h>
#include <math.h>

// ---------------- problem constants ----------------
#define NPTS   100000
#define DIN    128
#define D2     64
#define DOUT   256
#define KPTS   15
#define SIGMA  0.04f
#define NEG    0.1f
#define EPSBN  1e-5f
#define CAP    96

// ---------------- scratch (device globals; no runtime alloc) ----------------
__device__ float  g_t  [(size_t)NPTS * D2];      // fp32 GEMM out (t, then y)
__device__ float  g_u2 [(size_t)NPTS * DOUT];
__device__ float  g_usc[(size_t)NPTS * DOUT];
__device__ __align__(16) __nv_bfloat16 g_Sb [(size_t)NPTS * 2 * KPTS * D2];  // S split
__device__ __align__(16) __nv_bfloat16 g_w1b [D2   * 2 * DIN];   // Bt[n][2K]
__device__ __align__(16) __nv_bfloat16 g_wkpb[D2   * 2 * (KPTS*D2)];
__device__ __align__(16) __nv_bfloat16 g_w2b [DOUT * 2 * D2];
__device__ __align__(16) __nv_bfloat16 g_wscb[DOUT * 2 * DIN];
__device__ int    g_cnt[NPTS];
__device__ int    g_nbr[(size_t)NPTS * CAP];
__device__ double g_stats[1280];   // t:[0,128) y:[128,256) u2:[256,768) usc:[768,1280)
__device__ float2 g_bnp[640];      // (scale,shift): t:[0,64) y:[64,128) u2:[128,384) usc:[384,640)

// ---------------- small kernels ----------------
__global__ void zero_kernel() {
    int i = blockIdx.x * blockDim.x + threadIdx.x;
    if (i < NPTS) g_cnt[i] = 0;
    if (i < 1280) g_stats[i] = 0.0;
}

__global__ void scatter_kernel(const int* __restrict__ e_ref,
                               const int* __restrict__ e_qry, int E) {
    int e = blockIdx.x * blockDim.x + threadIdx.x;
    if (e >= E) return;
    int q = e_qry[e];
    int r = e_ref[e];
    int slot = atomicAdd(&g_cnt[q], 1);
    if (slot < CAP) g_nbr[(size_t)q * CAP + slot] = r;
}

__device__ __forceinline__ void bsplit(float v, __nv_bfloat16& h, __nv_bfloat16& l) {
    h = __float2bfloat16(v);
    l = __float2bfloat16(v - __bfloat162float(h));
}

// one write of one weight element, [K,N] fp32 -> [N,2K] bf16 hi|lo
__device__ __forceinline__ void wsplit_one(const float* W, __nv_bfloat16* out,
                                           int i, int K, int N) {
    int k = i / N, n = i % N;
    __nv_bfloat16 h, l;
    bsplit(W[i], h, l);
    out[(size_t)n * 2 * K + k] = h;
    out[(size_t)n * 2 * K + K + k] = l;
}

// fused: all four weight splits in one launch (flat index)
//  [0, 8192)       W1  K=128 N=64
//  [8192, 69632)   Wkp K=960 N=64
//  [69632, 86016)  W2  K=64  N=256
//  [86016, 118784) Wsc K=128 N=256
#define WSPLIT_TOTAL 118784
__global__ void wsplit_all(const float* __restrict__ W1, const float* __restrict__ Wkp,
                           const float* __restrict__ W2, const float* __restrict__ Wsc) {
    int i = blockIdx.x * blockDim.x + threadIdx.x;
    if (i >= WSPLIT_TOTAL) return;
    if (i < 8192) {
        wsplit_one(W1, g_w1b, i, DIN, D2);
    } else if (i < 69632) {
        wsplit_one(Wkp, g_wkpb, i - 8192, KPTS * D2, D2);
    } else if (i < 86016) {
        wsplit_one(W2, g_w2b, i - 69632, D2, DOUT);
    } else {
        wsplit_one(Wsc, g_wscb, i - 86016, DIN, DOUT);
    }
}

__global__ void bn_prep(int statOff, int C, const float* __restrict__ g,
                        const float* __restrict__ b, int prepOff, int M) {
    int i = threadIdx.x;
    if (i >= C) return;
    double m = g_stats[statOff + i] / (double)M;
    double v = g_stats[statOff + C + i] / (double)M - m * m;
    float rstd = rsqrtf((float)v + EPSBN);
    float scale = g[i] * rstd;
    float shift = b[i] - (float)m * scale;
    g_bnp[prepOff + i] = make_float2(scale, shift);
}

// fused: both 256-channel BN preps (u2 @stats 256->prep 128, usc @stats 768->prep 384)
__global__ void bn_prep2(const float* __restrict__ g2, const float* __restrict__ b2,
                         const float* __restrict__ gsc, const float* __restrict__ bsc,
                         int M) {
    int tid = threadIdx.x;
    int i = tid & 255;
    int which = tid >> 8;
    int statOff = which ? 768 : 256;
    int prepOff = which ? 384 : 128;
    const float* g = which ? gsc : g2;
    const float* b = which ? bsc : b2;
    double m = g_stats[statOff + i] / (double)M;
    double v = g_stats[statOff + DOUT + i] / (double)M - m * m;
    float rstd = rsqrtf((float)v + EPSBN);
    float scale = g[i] * rstd;
    float shift = b[i] - (float)m * scale;
    g_bnp[prepOff + i] = make_float2(scale, shift);
}

// ---------------- S build: serial per-warp loop (proven), BN+leaky fused ----------------
__global__ __launch_bounds__(256) void sbuild_kernel(
    const float* __restrict__ pos, const float* __restrict__ kp)
{
    __shared__ float skp[45];
    int tid = threadIdx.x;
    int lane = tid & 31;
    int warp = tid >> 5;
    if (tid < 45) skp[tid] = kp[tid];
    __syncthreads();

    int q = blockIdx.x * 8 + warp;
    if (q >= NPTS) return;

    float kx = 0.f, ky = 0.f, kz = 0.f;
    if (lane < KPTS) {
        kx = skp[lane * 3 + 0];
        ky = skp[lane * 3 + 1];
        kz = skp[lane * 3 + 2];
    }
    float2 p0 = __ldg(&g_bnp[2 * lane]);
    float2 p1 = __ldg(&g_bnp[2 * lane + 1]);

    float a0[KPTS], a1[KPTS];
#pragma unroll
    for (int k = 0; k < KPTS; ++k) { a0[k] = 0.f; a1[k] = 0.f; }

    float4 pq = __ldg((const float4*)pos + q);
    int cnt = g_cnt[q];
    if (cnt > CAP) cnt = CAP;
    const int* nb = g_nbr + (size_t)q * CAP;

    for (int j = 0; j < cnt; ++j) {
        int r = __ldg(&nb[j]);
        float4 pr = __ldg((const float4*)pos + r);
        float rx = pr.y - pq.y;
        float ry = pr.z - pq.z;
        float rz = pr.w - pq.w;
        float infl = 0.f;
        if (lane < KPTS) {
            float dx = rx - kx, dy = ry - ky, dz = rz - kz;
            float d2 = dx * dx + dy * dy + dz * dz;
            if (d2 < SIGMA * SIGMA)
                infl = 1.f - sqrtf(d2) * (1.f / SIGMA);
        }
        unsigned m = __ballot_sync(0xffffffffu, infl > 0.f);
        if (!m) continue;
        float2 hv = __ldg((const float2*)g_t + (size_t)r * 32 + lane);
        float h0 = fmaf(hv.x, p0.x, p0.y);
        h0 = (h0 >= 0.f) ? h0 : NEG * h0;
        float h1 = fmaf(hv.y, p1.x, p1.y);
        h1 = (h1 >= 0.f) ? h1 : NEG * h1;
#pragma unroll
        for (int k = 0; k < KPTS; ++k) {
            if (m & (1u << k)) {
                float w = __shfl_sync(0xffffffffu, infl, k);
                a0[k] += w * h0;
                a1[k] += w * h1;
            }
        }
    }

    __nv_bfloat162* Sout = (__nv_bfloat162*)(g_Sb + (size_t)q * 1920);
#pragma unroll
    for (int k = 0; k < KPTS; ++k) {
        __nv_bfloat16 h0, l0, h1, l1;
        bsplit(a0[k], h0, l0);
        bsplit(a1[k], h1, l1);
        __nv_bfloat162 hh; hh.x = h0; hh.y = h1;
        __nv_bfloat162 ll; ll.x = l0; ll.y = l1;
        Sout[k * 32 + lane] = hh;
        Sout[480 + k * 32 + lane] = ll;
    }
}

// ---------------- shared MMA helper ----------------
__device__ __forceinline__ void mma16816(float* c, const uint32_t* a, const uint32_t* b) {
    asm volatile(
        "mma.sync.aligned.m16n8k16.row.col.f32.bf16.bf16.f32 "
        "{%0,%1,%2,%3}, {%4,%5,%6,%7}, {%8,%9}, {%0,%1,%2,%3};"
        : "+f"(c[0]), "+f"(c[1]), "+f"(c[2]), "+f"(c[3])
        : "r"(a[0]), "r"(a[1]), "r"(a[2]), "r"(a[3]), "r"(b[0]), "r"(b[1]));
}

#define ROWP 72
#define SECA (128 * ROWP)
#define SECB (64 * ROWP)

// ---------------- gemm_mma (chunked-K, presplit A) — used only for the S GEMM ----------------
#define A_SEC (128 * ROWP)
#define B_SEC (64 * ROWP)
#define GSMEM_BYTES ((2 * A_SEC + 2 * B_SEC) * 2 + 512)

__global__ __launch_bounds__(256) void gemm_mma(
    const __nv_bfloat16* __restrict__ A,
    const __nv_bfloat16* __restrict__ B,
    float* __restrict__ C,
    int M, int K, int Nc, int statOff, int statC)
{
    extern __shared__ char smem[];
    __nv_bfloat16* sA = (__nv_bfloat16*)smem;
    __nv_bfloat16* sB = sA + 2 * A_SEC;
    float* red = (float*)(smem + (2 * A_SEC + 2 * B_SEC) * 2);

    const int tid = threadIdx.x;
    const int lane = tid & 31;
    const int wid = tid >> 5;
    const int wm = wid & 3;
    const int wn = wid >> 2;
    const int g = lane >> 2;
    const int t = lane & 3;
    const int m0 = blockIdx.x * 128;
    const int n0 = blockIdx.y * 64;
    const int lda = 2 * K;
    const int nch = K >> 6;

    if (tid < 128) red[tid] = 0.f;

    float acc[2][4][4];
#pragma unroll
    for (int mi = 0; mi < 2; ++mi)
#pragma unroll
        for (int ni = 0; ni < 4; ++ni)
#pragma unroll
            for (int j = 0; j < 4; ++j) acc[mi][ni][j] = 0.f;

    for (int c = 0; c < nch; ++c) {
        int koh = c * 64;
#pragma unroll
        for (int i = 0; i < 4; ++i) {
            int idx = tid + 256 * i;
            int r = idx >> 3, cw = idx & 7;
            int gr = m0 + r;
            uint4 vh = make_uint4(0, 0, 0, 0), vl = vh;
            if (gr < M) {
                const uint4* base = (const uint4*)(A + (size_t)gr * lda);
                vh = __ldg(base + (koh >> 3) + cw);
                vl = __ldg(base + ((K + koh) >> 3) + cw);
            }
            *(uint4*)(sA + r * ROWP + cw * 8) = vh;
            *(uint4*)(sA + A_SEC + r * ROWP + cw * 8) = vl;
        }
#pragma unroll
        for (int i = 0; i < 2; ++i) {
            int idx = tid + 256 * i;
            int r = idx >> 3, cw = idx & 7;
            const uint4* base = (const uint4*)(B + (size_t)(n0 + r) * lda);
            uint4 vh = __ldg(base + (koh >> 3) + cw);
            uint4 vl = __ldg(base + ((K + koh) >> 3) + cw);
            *(uint4*)(sB + r * ROWP + cw * 8) = vh;
            *(uint4*)(sB + B_SEC + r * ROWP + cw * 8) = vl;
        }
        __syncthreads();

#pragma unroll
        for (int ks = 0; ks < 4; ++ks) {
            int col = ks * 16 + 2 * t;
            uint32_t ah[2][4], al[2][4];
#pragma unroll
            for (int mi = 0; mi < 2; ++mi) {
                const __nv_bfloat16* p = sA + (wm * 32 + mi * 16 + g) * ROWP + col;
                ah[mi][0] = *(const uint32_t*)p;
                ah[mi][1] = *(const uint32_t*)(p + 8 * ROWP);
                ah[mi][2] = *(const uint32_t*)(p + 8);
                ah[mi][3] = *(const uint32_t*)(p + 8 * ROWP + 8);
                const __nv_bfloat16* qp = p + A_SEC;
                al[mi][0] = *(const uint32_t*)qp;
                al[mi][1] = *(const uint32_t*)(qp + 8 * ROWP);
                al[mi][2] = *(const uint32_t*)(qp + 8);
                al[mi][3] = *(const uint32_t*)(qp + 8 * ROWP + 8);
            }
            uint32_t bh[4][2], bl[4][2];
#pragma unroll
            for (int ni = 0; ni < 4; ++ni) {
                const __nv_bfloat16* p = sB + (wn * 32 + ni * 8 + g) * ROWP + col;
                bh[ni][0] = *(const uint32_t*)p;
                bh[ni][1] = *(const uint32_t*)(p + 8);
                const __nv_bfloat16* qp = p + B_SEC;
                bl[ni][0] = *(const uint32_t*)qp;
                bl[ni][1] = *(const uint32_t*)(qp + 8);
            }
#pragma unroll
            for (int mi = 0; mi < 2; ++mi)
#pragma unroll
                for (int ni = 0; ni < 4; ++ni) {
                    mma16816(acc[mi][ni], ah[mi], bh[ni]);
                    mma16816(acc[mi][ni], ah[mi], bl[ni]);
                    mma16816(acc[mi][ni], al[mi], bh[ni]);
                }
        }
        __syncthreads();
    }

#pragma unroll
    for (int ni = 0; ni < 4; ++ni) {
        int colL = wn * 32 + ni * 8 + 2 * t;
        float s0 = 0.f, q0 = 0.f, s1 = 0.f, q1 = 0.f;
#pragma unroll
        for (int mi = 0; mi < 2; ++mi) {
            float* f = acc[mi][ni];
            int row = m0 + wm * 32 + mi * 16 + g;
            if (row < M) {
                C[(size_t)row * Nc + n0 + colL] = f[0];
                C[(size_t)row * Nc + n0 + colL + 1] = f[1];
                s0 += f[0]; q0 += f[0] * f[0];
                s1 += f[1]; q1 += f[1] * f[1];
            }
            if (row + 8 < M) {
                C[(size_t)(row + 8) * Nc + n0 + colL] = f[2];
                C[(size_t)(row + 8) * Nc + n0 + colL + 1] = f[3];
                s0 += f[2]; q0 += f[2] * f[2];
                s1 += f[3]; q1 += f[3] * f[3];
            }
        }
#pragma unroll
        for (int off = 4; off < 32; off <<= 1) {
            s0 += __shfl_xor_sync(0xffffffffu, s0, off);
            q0 += __shfl_xor_sync(0xffffffffu, q0, off);
            s1 += __shfl_xor_sync(0xffffffffu, s1, off);
            q1 += __shfl_xor_sync(0xffffffffu, q1, off);
        }
        if (g == 0) {
            atomicAdd(&red[colL], s0);
            atomicAdd(&red[64 + colL], q0);
            atomicAdd(&red[colL + 1], s1);
            atomicAdd(&red[64 + colL + 1], q1);
        }
    }
    __syncthreads();
    if (tid < 64) {
        atomicAdd(&g_stats[statOff + n0 + tid], (double)red[tid]);
        atomicAdd(&g_stats[statOff + statC + n0 + tid], (double)red[64 + tid]);
    }
}

// ---------------- gemm_wide: fp32 A staged once with inline split (+BN for AMODE 2) ----------------
template <int AMODE>
__global__ __launch_bounds__(256) void gemm_wide(
    const float* __restrict__ A32,
    const __nv_bfloat16* __restrict__ B,
    float* __restrict__ C,
    int M, int K, int Nc, int statOff, int prepOff)
{
    extern __shared__ char smem[];
    const int nch = K >> 6;
    const int ntiles = Nc >> 6;
    __nv_bfloat16* sA = (__nv_bfloat16*)smem;
    __nv_bfloat16* sB = sA + 2 * nch * SECA;
    float* red = (float*)(sB + 2 * nch * SECB);

    const int tid = threadIdx.x;
    const int lane = tid & 31;
    const int wid = tid >> 5;
    const int wm = wid & 3;
    const int wn = wid >> 2;
    const int g = lane >> 2;
    const int t = lane & 3;
    const int m0 = blockIdx.x * 128;
    const int ldb = 2 * K;

    for (int c = 0; c < nch; ++c) {
        __nv_bfloat16* dAh = sA + (2 * c) * SECA;
        __nv_bfloat16* dAl = dAh + SECA;
        int koh = c * 64;
#pragma unroll
        for (int i = 0; i < 8; ++i) {
            int idx = tid + 256 * i;
            int r = idx >> 4;
            int cc = (idx & 15) * 4;
            int gr = m0 + r;
            float4 v = make_float4(0.f, 0.f, 0.f, 0.f);
            if (gr < M)
                v = __ldg((const float4*)(A32 + (size_t)gr * K + koh + cc));
            __nv_bfloat16 h[4], l[4];
#pragma unroll
            for (int j = 0; j < 4; ++j) {
                float u = (&v.x)[j];
                if (AMODE == 2) {
                    float2 p = __ldg(&g_bnp[prepOff + koh + cc + j]);
                    u = fmaf(u, p.x, p.y);
                    u = (u >= 0.f) ? u : NEG * u;
                }
                bsplit(u, h[j], l[j]);
            }
            __nv_bfloat162 h01, h23, l01, l23;
            h01.x = h[0]; h01.y = h[1]; h23.x = h[2]; h23.y = h[3];
            l01.x = l[0]; l01.y = l[1]; l23.x = l[2]; l23.y = l[3];
            uint2 hp, lp;
            hp.x = *(uint32_t*)&h01; hp.y = *(uint32_t*)&h23;
            lp.x = *(uint32_t*)&l01; lp.y = *(uint32_t*)&l23;
            *(uint2*)(dAh + r * ROWP + cc) = hp;
            *(uint2*)(dAl + r * ROWP + cc) = lp;
        }
    }

    for (int nt = 0; nt < ntiles; ++nt) {
        int n0 = nt * 64;
        if (tid < 128) red[tid] = 0.f;
        for (int c = 0; c < nch; ++c) {
            __nv_bfloat16* dBh = sB + (2 * c) * SECB;
            __nv_bfloat16* dBl = dBh + SECB;
            int koh = c * 64;
#pragma unroll
            for (int i = 0; i < 2; ++i) {
                int idx = tid + 256 * i;
                int r = idx >> 3, cw = idx & 7;
                const uint4* base = (const uint4*)(B + (size_t)(n0 + r) * ldb);
                uint4 vh = __ldg(base + (koh >> 3) + cw);
                uint4 vl = __ldg(base + ((K + koh) >> 3) + cw);
                *(uint4*)(dBh + r * ROWP + cw * 8) = vh;
                *(uint4*)(dBl + r * ROWP + cw * 8) = vl;
            }
        }
        __syncthreads();

        float acc[2][4][4];
#pragma unroll
        for (int mi = 0; mi < 2; ++mi)
#pragma unroll
            for (int ni = 0; ni < 4; ++ni)
#pragma unroll
                for (int j = 0; j < 4; ++j) acc[mi][ni][j] = 0.f;

        for (int c = 0; c < nch; ++c) {
            const __nv_bfloat16* pAh = sA + (2 * c) * SECA;
            const __nv_bfloat16* pAl = pAh + SECA;
            const __nv_bfloat16* pBh = sB + (2 * c) * SECB;
            const __nv_bfloat16* pBl = pBh + SECB;
#pragma unroll
            for (int ks = 0; ks < 4; ++ks) {
                int col = ks * 16 + 2 * t;
                uint32_t ah[2][4], al[2][4];
#pragma unroll
                for (int mi = 0; mi < 2; ++mi) {
                    const __nv_bfloat16* p = pAh + (wm * 32 + mi * 16 + g) * ROWP + col;
                    ah[mi][0] = *(const uint32_t*)p;
                    ah[mi][1] = *(const uint32_t*)(p + 8 * ROWP);
                    ah[mi][2] = *(const uint32_t*)(p + 8);
                    ah[mi][3] = *(const uint32_t*)(p + 8 * ROWP + 8);
                    const __nv_bfloat16* qp = pAl + (wm * 32 + mi * 16 + g) * ROWP + col;
                    al[mi][0] = *(const uint32_t*)qp;
                    al[mi][1] = *(const uint32_t*)(qp + 8 * ROWP);
                    al[mi][2] = *(const uint32_t*)(qp + 8);
                    al[mi][3] = *(const uint32_t*)(qp + 8 * ROWP + 8);
                }
                uint32_t bh[4][2], bl[4][2];
#pragma unroll
                for (int ni = 0; ni < 4; ++ni) {
                    const __nv_bfloat16* p = pBh + (wn * 32 + ni * 8 + g) * ROWP + col;
                    bh[ni][0] = *(const uint32_t*)p;
                    bh[ni][1] = *(const uint32_t*)(p + 8);
                    const __nv_bfloat16* qp = pBl + (wn * 32 + ni * 8 + g) * ROWP + col;
                    bl[ni][0] = *(const uint32_t*)qp;
                    bl[ni][1] = *(const uint32_t*)(qp + 8);
                }
#pragma unroll
                for (int mi = 0; mi < 2; ++mi)
#pragma unroll
                    for (int ni = 0; ni < 4; ++ni) {
                        mma16816(acc[mi][ni], ah[mi], bh[ni]);
                        mma16816(acc[mi][ni], ah[mi], bl[ni]);
                        mma16816(acc[mi][ni], al[mi], bh[ni]);
                    }
            }
        }

#pragma unroll
        for (int ni = 0; ni < 4; ++ni) {
            int colL = wn * 32 + ni * 8 + 2 * t;
            float s0 = 0.f, q0 = 0.f, s1 = 0.f, q1 = 0.f;
#pragma unroll
            for (int mi = 0; mi < 2; ++mi) {
                float* f = acc[mi][ni];
                int row = m0 + wm * 32 + mi * 16 + g;
                if (row < M) {
                    C[(size_t)row * Nc + n0 + colL] = f[0];
                    C[(size_t)row * Nc + n0 + colL + 1] = f[1];
                    s0 += f[0]; q0 += f[0] * f[0];
                    s1 += f[1]; q1 += f[1] * f[1];
                }
                if (row + 8 < M) {
                    C[(size_t)(row + 8) * Nc + n0 + colL] = f[2];
                    C[(size_t)(row + 8) * Nc + n0 + colL + 1] = f[3];
                    s0 += f[2]; q0 += f[2] * f[2];
                    s1 += f[3]; q1 += f[3] * f[3];
                }
            }
#pragma unroll
            for (int off = 4; off < 32; off <<= 1) {
                s0 += __shfl_xor_sync(0xffffffffu, s0, off);
                q0 += __shfl_xor_sync(0xffffffffu, q0, off);
                s1 += __shfl_xor_sync(0xffffffffu, s1, off);
                q1 += __shfl_xor_sync(0xffffffffu, q1, off);
            }
            if (g == 0) {
                atomicAdd(&red[colL], s0);
                atomicAdd(&red[64 + colL], q0);
                atomicAdd(&red[colL + 1], s1);
                atomicAdd(&red[64 + colL + 1], q1);
            }
        }
        __syncthreads();
        if (tid < 64) {
            atomicAdd(&g_stats[statOff + n0 + tid], (double)red[tid]);
            atomicAdd(&g_stats[statOff + Nc + n0 + tid], (double)red[64 + tid]);
        }
        __syncthreads();
    }
}

// ---------------- final: out = leaky(bn(u2)) + bn(usc), float4 ----------------
__global__ void final_kernel(float4* __restrict__ out, int n4) {
    int i = blockIdx.x * blockDim.x + threadIdx.x;
    if (i >= n4) return;
    int c4 = (i & 63) * 4;
    float4 a = __ldg((const float4*)g_u2 + i);
    float4 s = __ldg((const float4*)g_usc + i);
    float4 o;
#pragma unroll
    for (int j = 0; j < 4; ++j) {
        float2 p2 = __ldg(&g_bnp[128 + c4 + j]);
        float2 ps = __ldg(&g_bnp[384 + c4 + j]);
        float u = fmaf((&a.x)[j], p2.x, p2.y);
        u = (u >= 0.f) ? u : NEG * u;
        (&o.x)[j] = u + fmaf((&s.x)[j], ps.x, ps.y);
    }
    out[i] = o;
}

// ---------------- launch ----------------
extern "C" void kernel_launch(void* const* d_in, const int* in_sizes, int n_in,
                              void* d_out, int out_size) {
    const float* pos    = (const float*)d_in[0];
    const float* x      = (const float*)d_in[1];
    const int*   e_ref  = (const int*)  d_in[2];
    const int*   e_qry  = (const int*)  d_in[3];
    const float* W1     = (const float*)d_in[4];
    const float* g1     = (const float*)d_in[5];
    const float* b1     = (const float*)d_in[6];
    const float* kp     = (const float*)d_in[7];
    const float* Wkp    = (const float*)d_in[8];
    const float* gkp    = (const float*)d_in[9];
    const float* bkp    = (const float*)d_in[10];
    const float* W2     = (const float*)d_in[11];
    const float* g2     = (const float*)d_in[12];
    const float* b2     = (const float*)d_in[13];
    const float* Wsc    = (const float*)d_in[14];
    const float* gsc    = (const float*)d_in[15];
    const float* bsc    = (const float*)d_in[16];
    float* out = (float*)d_out;

    const int M = NPTS;
    const int E = in_sizes[2];

    float *t_p, *u2_p, *usc_p;
    __nv_bfloat16 *Sb_p, *wkpb_p, *w1b_p, *w2b_p, *wscb_p;
    cudaGetSymbolAddress((void**)&t_p,    g_t);
    cudaGetSymbolAddress((void**)&u2_p,   g_u2);
    cudaGetSymbolAddress((void**)&usc_p,  g_usc);
    cudaGetSymbolAddress((void**)&Sb_p,   g_Sb);
    cudaGetSymbolAddress((void**)&w1b_p,  g_w1b);
    cudaGetSymbolAddress((void**)&wkpb_p, g_wkpb);
    cudaGetSymbolAddress((void**)&w2b_p,  g_w2b);
    cudaGetSymbolAddress((void**)&wscb_p, g_wscb);

    cudaFuncSetAttribute(gemm_mma, cudaFuncAttributeMaxDynamicSharedMemorySize, GSMEM_BYTES);
    const int GW_SMEM_K128 = 4 * (SECA + SECB) * 2 + 512;
    const int GW_SMEM_K64  = 2 * (SECA + SECB) * 2 + 512;
    cudaFuncSetAttribute(gemm_wide<1>, cudaFuncAttributeMaxDynamicSharedMemorySize, GW_SMEM_K128);
    cudaFuncSetAttribute(gemm_wide<2>, cudaFuncAttributeMaxDynamicSharedMemorySize, GW_SMEM_K128);

    const int MB = (M + 127) / 128;
    int n4_256 = M * DOUT / 4;

    // launch order chosen so ncu (-s 5 -c 1) profiles sbuild_kernel (#6)
    // 1. zero counters + stats
    zero_kernel<<<(NPTS + 255) / 256, 256>>>();
    // 2. all weight splits (one launch)
    wsplit_all<<<(WSPLIT_TOTAL + 255) / 256, 256>>>(W1, Wkp, W2, Wsc);
    // 3. bin edges by query
    scatter_kernel<<<(E + 255) / 256, 256>>>(e_ref, e_qry, E);
    // 4. t = x @ W1   (fp32 A inline-split; K=128, Nc=64, stats @0)
    gemm_wide<1><<<MB, 256, GW_SMEM_K128>>>(x, w1b_p, t_p, M, DIN, D2, 0, 0);
    // 5. BN params for t
    bn_prep<<<1, 64>>>(0, D2, g1, b1, 0, M);
    // 6. build split-bf16 S (BN+leaky fused)  <-- profiled launch
    sbuild_kernel<<<(M + 7) / 8, 256>>>(pos, kp);
    // 7. y = S @ Wkp  (K=960, Nc=64, stats @128) -> g_t
    gemm_mma<<<dim3(MB, 1), 256, GSMEM_BYTES>>>(Sb_p, wkpb_p, t_p, M, KPTS * D2, D2, 128, D2);
    // 8. BN params for y
    bn_prep<<<1, 64>>>(128, D2, gkp, bkp, 64, M);
    // 9. u2 = leaky(bn(y)) @ W2  (BN+leaky fused into A staging)
    gemm_wide<2><<<MB, 256, GW_SMEM_K64>>>(t_p, w2b_p, u2_p, M, D2, DOUT, 256, 64);
    // 10. usc = x @ Wsc
    gemm_wide<1><<<MB, 256, GW_SMEM_K128>>>(x, wscb_p, usc_p, M, DIN, DOUT, 768, 0);
    // 11. both 256-wide BN preps in one launch
    bn_prep2<<<1, 512>>>(g2, b2, gsc, bsc, M);
    // 12. output
    final_kernel<<<(n4_256 + 255) / 256, 256>>>((float4*)out, n4_256);
}

// round 12
// speedup vs baseline: 1.0613x; 1.0613x over previous
#include <cuda_runtime.h>
#include <cuda_bf16.h>
#include <stdint.h>
#include <math.h>

// ---------------- problem constants ----------------
#define NPTS   100000
#define DIN    128
#define D2     64
#define DOUT   256
#define KPTS   15
#define SIGMA  0.04f
#define NEG    0.1f
#define EPSBN  1e-5f
#define CAP    96

// ---------------- scratch (device globals; no runtime alloc) ----------------
__device__ float  g_t  [(size_t)NPTS * D2];      // fp32 GEMM out (t, then y)
__device__ float  g_u2 [(size_t)NPTS * DOUT];
__device__ float  g_usc[(size_t)NPTS * DOUT];
__device__ __align__(16) __nv_bfloat16 g_Sb [(size_t)NPTS * 2 * KPTS * D2];  // S split
__device__ __align__(16) __nv_bfloat16 g_w1b [D2   * 2 * DIN];   // Bt[n][2K]
__device__ __align__(16) __nv_bfloat16 g_wkpb[D2   * 2 * (KPTS*D2)];
__device__ __align__(16) __nv_bfloat16 g_w2b [DOUT * 2 * D2];
__device__ __align__(16) __nv_bfloat16 g_wscb[DOUT * 2 * DIN];
__device__ int    g_cnt[NPTS];
__device__ int    g_nbr[(size_t)NPTS * CAP];
__device__ double g_stats[1280];   // t:[0,128) y:[128,256) u2:[256,768) usc:[768,1280)
__device__ float2 g_bnp[640];      // (scale,shift): t:[0,64) y:[64,128) u2:[128,384) usc:[384,640)

// ---------------- small kernels ----------------
__global__ void zero_kernel() {
    int i = blockIdx.x * blockDim.x + threadIdx.x;
    if (i < NPTS) g_cnt[i] = 0;
    if (i < 1280) g_stats[i] = 0.0;
}

__global__ void scatter_kernel(const int* __restrict__ e_ref,
                               const int* __restrict__ e_qry, int E) {
    int e = blockIdx.x * blockDim.x + threadIdx.x;
    if (e >= E) return;
    int q = e_qry[e];
    int r = e_ref[e];
    int slot = atomicAdd(&g_cnt[q], 1);
    if (slot < CAP) g_nbr[(size_t)q * CAP + slot] = r;
}

__device__ __forceinline__ void bsplit(float v, __nv_bfloat16& h, __nv_bfloat16& l) {
    h = __float2bfloat16(v);
    l = __float2bfloat16(v - __bfloat162float(h));
}

// one write of one weight element, [K,N] fp32 -> [N,2K] bf16 hi|lo
__device__ __forceinline__ void wsplit_one(const float* W, __nv_bfloat16* out,
                                           int i, int K, int N) {
    int k = i / N, n = i % N;
    __nv_bfloat16 h, l;
    bsplit(W[i], h, l);
    out[(size_t)n * 2 * K + k] = h;
    out[(size_t)n * 2 * K + K + k] = l;
}

#define WSPLIT_TOTAL 118784
__global__ void wsplit_all(const float* __restrict__ W1, const float* __restrict__ Wkp,
                           const float* __restrict__ W2, const float* __restrict__ Wsc) {
    int i = blockIdx.x * blockDim.x + threadIdx.x;
    if (i >= WSPLIT_TOTAL) return;
    if (i < 8192) {
        wsplit_one(W1, g_w1b, i, DIN, D2);
    } else if (i < 69632) {
        wsplit_one(Wkp, g_wkpb, i - 8192, KPTS * D2, D2);
    } else if (i < 86016) {
        wsplit_one(W2, g_w2b, i - 69632, D2, DOUT);
    } else {
        wsplit_one(Wsc, g_wscb, i - 86016, DIN, DOUT);
    }
}

__global__ void bn_prep(int statOff, int C, const float* __restrict__ g,
                        const float* __restrict__ b, int prepOff, int M) {
    int i = threadIdx.x;
    if (i >= C) return;
    double m = g_stats[statOff + i] / (double)M;
    double v = g_stats[statOff + C + i] / (double)M - m * m;
    float rstd = rsqrtf((float)v + EPSBN);
    float scale = g[i] * rstd;
    float shift = b[i] - (float)m * scale;
    g_bnp[prepOff + i] = make_float2(scale, shift);
}

__global__ void bn_prep2(const float* __restrict__ g2, const float* __restrict__ b2,
                         const float* __restrict__ gsc, const float* __restrict__ bsc,
                         int M) {
    int tid = threadIdx.x;
    int i = tid & 255;
    int which = tid >> 8;
    int statOff = which ? 768 : 256;
    int prepOff = which ? 384 : 128;
    const float* g = which ? gsc : g2;
    const float* b = which ? bsc : b2;
    double m = g_stats[statOff + i] / (double)M;
    double v = g_stats[statOff + DOUT + i] / (double)M - m * m;
    float rstd = rsqrtf((float)v + EPSBN);
    float scale = g[i] * rstd;
    float shift = b[i] - (float)m * scale;
    g_bnp[prepOff + i] = make_float2(scale, shift);
}

// ---------------- S build: serial per-warp loop (proven), BN+leaky fused ----------------
__global__ __launch_bounds__(256) void sbuild_kernel(
    const float* __restrict__ pos, const float* __restrict__ kp)
{
    __shared__ float skp[45];
    int tid = threadIdx.x;
    int lane = tid & 31;
    int warp = tid >> 5;
    if (tid < 45) skp[tid] = kp[tid];
    __syncthreads();

    int q = blockIdx.x * 8 + warp;
    if (q >= NPTS) return;

    float kx = 0.f, ky = 0.f, kz = 0.f;
    if (lane < KPTS) {
        kx = skp[lane * 3 + 0];
        ky = skp[lane * 3 + 1];
        kz = skp[lane * 3 + 2];
    }
    float2 p0 = __ldg(&g_bnp[2 * lane]);
    float2 p1 = __ldg(&g_bnp[2 * lane + 1]);

    float a0[KPTS], a1[KPTS];
#pragma unroll
    for (int k = 0; k < KPTS; ++k) { a0[k] = 0.f; a1[k] = 0.f; }

    float4 pq = __ldg((const float4*)pos + q);
    int cnt = g_cnt[q];
    if (cnt > CAP) cnt = CAP;
    const int* nb = g_nbr + (size_t)q * CAP;

    for (int j = 0; j < cnt; ++j) {
        int r = __ldg(&nb[j]);
        float4 pr = __ldg((const float4*)pos + r);
        float rx = pr.y - pq.y;
        float ry = pr.z - pq.z;
        float rz = pr.w - pq.w;
        float infl = 0.f;
        if (lane < KPTS) {
            float dx = rx - kx, dy = ry - ky, dz = rz - kz;
            float d2 = dx * dx + dy * dy + dz * dz;
            if (d2 < SIGMA * SIGMA)
                infl = 1.f - sqrtf(d2) * (1.f / SIGMA);
        }
        unsigned m = __ballot_sync(0xffffffffu, infl > 0.f);
        if (!m) continue;
        float2 hv = __ldg((const float2*)g_t + (size_t)r * 32 + lane);
        float h0 = fmaf(hv.x, p0.x, p0.y);
        h0 = (h0 >= 0.f) ? h0 : NEG * h0;
        float h1 = fmaf(hv.y, p1.x, p1.y);
        h1 = (h1 >= 0.f) ? h1 : NEG * h1;
#pragma unroll
        for (int k = 0; k < KPTS; ++k) {
            if (m & (1u << k)) {
                float w = __shfl_sync(0xffffffffu, infl, k);
                a0[k] += w * h0;
                a1[k] += w * h1;
            }
        }
    }

    __nv_bfloat162* Sout = (__nv_bfloat162*)(g_Sb + (size_t)q * 1920);
#pragma unroll
    for (int k = 0; k < KPTS; ++k) {
        __nv_bfloat16 h0, l0, h1, l1;
        bsplit(a0[k], h0, l0);
        bsplit(a1[k], h1, l1);
        __nv_bfloat162 hh; hh.x = h0; hh.y = h1;
        __nv_bfloat162 ll; ll.x = l0; ll.y = l1;
        Sout[k * 32 + lane] = hh;
        Sout[480 + k * 32 + lane] = ll;
    }
}

// ---------------- MMA / LDSM helpers ----------------
__device__ __forceinline__ void mma16816(float* c, const uint32_t* a, const uint32_t* b) {
    asm volatile(
        "mma.sync.aligned.m16n8k16.row.col.f32.bf16.bf16.f32 "
        "{%0,%1,%2,%3}, {%4,%5,%6,%7}, {%8,%9}, {%0,%1,%2,%3};"
        : "+f"(c[0]), "+f"(c[1]), "+f"(c[2]), "+f"(c[3])
        : "r"(a[0]), "r"(a[1]), "r"(a[2]), "r"(a[3]), "r"(b[0]), "r"(b[1]));
}

#define LDSM4(r, addr) \
    asm volatile("ldmatrix.sync.aligned.m8n8.x4.shared.b16 {%0,%1,%2,%3}, [%4];" \
        : "=r"((r)[0]), "=r"((r)[1]), "=r"((r)[2]), "=r"((r)[3]) : "r"(addr))

#define ROWP 72
#define SECA (128 * ROWP)
#define SECB (64 * ROWP)

// lane-dependent LDSM byte offsets (constant across ks/chunks)
// A x4: row = base + (lane&15); col += (lane>>4)*8
// B x4 (covers ni pair): row = base + ((lane>>4)<<3) + (lane&7); col += ((lane>>3)&1)*8
struct LdsmOff {
    uint32_t a0, a1, b0, b1;
};
__device__ __forceinline__ LdsmOff ldsm_offsets(int wm, int wn, int lane) {
    LdsmOff o;
    int aRow = wm * 32 + (lane & 15);
    int aCol = ((lane >> 4) & 1) * 8;
    o.a0 = (uint32_t)((aRow * ROWP + aCol) * 2);
    o.a1 = (uint32_t)(((aRow + 16) * ROWP + aCol) * 2);
    int bRow = wn * 32 + (((lane >> 4) & 1) << 3) + (lane & 7);
    int bCol = ((lane >> 3) & 1) * 8;
    o.b0 = (uint32_t)((bRow * ROWP + bCol) * 2);
    o.b1 = (uint32_t)(((bRow + 16) * ROWP + bCol) * 2);
    return o;
}

// inner product step on one staged chunk (hi/lo sections at uAh/uAl/uBh/uBl)
__device__ __forceinline__ void mma_chunk(
    float acc[2][4][4], const LdsmOff& o,
    uint32_t uAh, uint32_t uAl, uint32_t uBh, uint32_t uBl)
{
#pragma unroll
    for (int ks = 0; ks < 4; ++ks) {
        uint32_t cb = ks * 32;   // 16 bf16 = 32 bytes
        uint32_t ah[2][4], al[2][4], bh[2][4], bl[2][4];
        LDSM4(ah[0], uAh + o.a0 + cb);
        LDSM4(ah[1], uAh + o.a1 + cb);
        LDSM4(al[0], uAl + o.a0 + cb);
        LDSM4(al[1], uAl + o.a1 + cb);
        LDSM4(bh[0], uBh + o.b0 + cb);
        LDSM4(bh[1], uBh + o.b1 + cb);
        LDSM4(bl[0], uBl + o.b0 + cb);
        LDSM4(bl[1], uBl + o.b1 + cb);
#pragma unroll
        for (int mi = 0; mi < 2; ++mi)
#pragma unroll
            for (int ni = 0; ni < 4; ++ni) {
                const uint32_t* pbh = &bh[ni >> 1][(ni & 1) * 2];
                const uint32_t* pbl = &bl[ni >> 1][(ni & 1) * 2];
                mma16816(acc[mi][ni], ah[mi], pbh);
                mma16816(acc[mi][ni], ah[mi], pbl);
                mma16816(acc[mi][ni], al[mi], pbh);
            }
    }
}

// ---------------- gemm_mma (chunked-K, presplit A) — used only for the S GEMM ----------------
#define A_SEC (128 * ROWP)
#define B_SEC (64 * ROWP)
#define GSMEM_BYTES ((2 * A_SEC + 2 * B_SEC) * 2 + 512)

__global__ __launch_bounds__(256) void gemm_mma(
    const __nv_bfloat16* __restrict__ A,
    const __nv_bfloat16* __restrict__ B,
    float* __restrict__ C,
    int M, int K, int Nc, int statOff, int statC)
{
    extern __shared__ char smem[];
    __nv_bfloat16* sA = (__nv_bfloat16*)smem;
    __nv_bfloat16* sB = sA + 2 * A_SEC;
    float* red = (float*)(smem + (2 * A_SEC + 2 * B_SEC) * 2);

    const int tid = threadIdx.x;
    const int lane = tid & 31;
    const int wid = tid >> 5;
    const int wm = wid & 3;
    const int wn = wid >> 2;
    const int g = lane >> 2;
    const int t = lane & 3;
    const int m0 = blockIdx.x * 128;
    const int n0 = blockIdx.y * 64;
    const int lda = 2 * K;
    const int nch = K >> 6;

    const LdsmOff off = ldsm_offsets(wm, wn, lane);
    const uint32_t uAh = (uint32_t)__cvta_generic_to_shared(sA);
    const uint32_t uAl = uAh + A_SEC * 2;
    const uint32_t uBh = (uint32_t)__cvta_generic_to_shared(sB);
    const uint32_t uBl = uBh + B_SEC * 2;

    if (tid < 128) red[tid] = 0.f;

    float acc[2][4][4];
#pragma unroll
    for (int mi = 0; mi < 2; ++mi)
#pragma unroll
        for (int ni = 0; ni < 4; ++ni)
#pragma unroll
            for (int j = 0; j < 4; ++j) acc[mi][ni][j] = 0.f;

    for (int c = 0; c < nch; ++c) {
        int koh = c * 64;
#pragma unroll
        for (int i = 0; i < 4; ++i) {
            int idx = tid + 256 * i;
            int r = idx >> 3, cw = idx & 7;
            int gr = m0 + r;
            uint4 vh = make_uint4(0, 0, 0, 0), vl = vh;
            if (gr < M) {
                const uint4* base = (const uint4*)(A + (size_t)gr * lda);
                vh = __ldg(base + (koh >> 3) + cw);
                vl = __ldg(base + ((K + koh) >> 3) + cw);
            }
            *(uint4*)(sA + r * ROWP + cw * 8) = vh;
            *(uint4*)(sA + A_SEC + r * ROWP + cw * 8) = vl;
        }
#pragma unroll
        for (int i = 0; i < 2; ++i) {
            int idx = tid + 256 * i;
            int r = idx >> 3, cw = idx & 7;
            const uint4* base = (const uint4*)(B + (size_t)(n0 + r) * lda);
            uint4 vh = __ldg(base + (koh >> 3) + cw);
            uint4 vl = __ldg(base + ((K + koh) >> 3) + cw);
            *(uint4*)(sB + r * ROWP + cw * 8) = vh;
            *(uint4*)(sB + B_SEC + r * ROWP + cw * 8) = vl;
        }
        __syncthreads();
        mma_chunk(acc, off, uAh, uAl, uBh, uBl);
        __syncthreads();
    }

#pragma unroll
    for (int ni = 0; ni < 4; ++ni) {
        int colL = wn * 32 + ni * 8 + 2 * t;
        float s0 = 0.f, q0 = 0.f, s1 = 0.f, q1 = 0.f;
#pragma unroll
        for (int mi = 0; mi < 2; ++mi) {
            float* f = acc[mi][ni];
            int row = m0 + wm * 32 + mi * 16 + g;
            if (row < M) {
                C[(size_t)row * Nc + n0 + colL] = f[0];
                C[(size_t)row * Nc + n0 + colL + 1] = f[1];
                s0 += f[0]; q0 += f[0] * f[0];
                s1 += f[1]; q1 += f[1] * f[1];
            }
            if (row + 8 < M) {
                C[(size_t)(row + 8) * Nc + n0 + colL] = f[2];
                C[(size_t)(row + 8) * Nc + n0 + colL + 1] = f[3];
                s0 += f[2]; q0 += f[2] * f[2];
                s1 += f[3]; q1 += f[3] * f[3];
            }
        }
#pragma unroll
        for (int off2 = 4; off2 < 32; off2 <<= 1) {
            s0 += __shfl_xor_sync(0xffffffffu, s0, off2);
            q0 += __shfl_xor_sync(0xffffffffu, q0, off2);
            s1 += __shfl_xor_sync(0xffffffffu, s1, off2);
            q1 += __shfl_xor_sync(0xffffffffu, q1, off2);
        }
        if (g == 0) {
            atomicAdd(&red[colL], s0);
            atomicAdd(&red[64 + colL], q0);
            atomicAdd(&red[colL + 1], s1);
            atomicAdd(&red[64 + colL + 1], q1);
        }
    }
    __syncthreads();
    if (tid < 64) {
        atomicAdd(&g_stats[statOff + n0 + tid], (double)red[tid]);
        atomicAdd(&g_stats[statOff + statC + n0 + tid], (double)red[64 + tid]);
    }
}

// ---------------- gemm_wide: fp32 A staged once with inline split (+BN for AMODE 2) ----------------
template <int AMODE>
__global__ __launch_bounds__(256) void gemm_wide(
    const float* __restrict__ A32,
    const __nv_bfloat16* __restrict__ B,
    float* __restrict__ C,
    int M, int K, int Nc, int statOff, int prepOff)
{
    extern __shared__ char smem[];
    const int nch = K >> 6;
    const int ntiles = Nc >> 6;
    __nv_bfloat16* sA = (__nv_bfloat16*)smem;
    __nv_bfloat16* sB = sA + 2 * nch * SECA;
    float* red = (float*)(sB + 2 * nch * SECB);

    const int tid = threadIdx.x;
    const int lane = tid & 31;
    const int wid = tid >> 5;
    const int wm = wid & 3;
    const int wn = wid >> 2;
    const int g = lane >> 2;
    const int t = lane & 3;
    const int m0 = blockIdx.x * 128;
    const int ldb = 2 * K;

    const LdsmOff off = ldsm_offsets(wm, wn, lane);
    const uint32_t uA = (uint32_t)__cvta_generic_to_shared(sA);
    const uint32_t uB = (uint32_t)__cvta_generic_to_shared(sB);

    for (int c = 0; c < nch; ++c) {
        __nv_bfloat16* dAh = sA + (2 * c) * SECA;
        __nv_bfloat16* dAl = dAh + SECA;
        int koh = c * 64;
#pragma unroll
        for (int i = 0; i < 8; ++i) {
            int idx = tid + 256 * i;
            int r = idx >> 4;
            int cc = (idx & 15) * 4;
            int gr = m0 + r;
            float4 v = make_float4(0.f, 0.f, 0.f, 0.f);
            if (gr < M)
                v = __ldg((const float4*)(A32 + (size_t)gr * K + koh + cc));
            __nv_bfloat16 h[4], l[4];
#pragma unroll
            for (int j = 0; j < 4; ++j) {
                float u = (&v.x)[j];
                if (AMODE == 2) {
                    float2 p = __ldg(&g_bnp[prepOff + koh + cc + j]);
                    u = fmaf(u, p.x, p.y);
                    u = (u >= 0.f) ? u : NEG * u;
                }
                bsplit(u, h[j], l[j]);
            }
            __nv_bfloat162 h01, h23, l01, l23;
            h01.x = h[0]; h01.y = h[1]; h23.x = h[2]; h23.y = h[3];
            l01.x = l[0]; l01.y = l[1]; l23.x = l[2]; l23.y = l[3];
            uint2 hp, lp;
            hp.x = *(uint32_t*)&h01; hp.y = *(uint32_t*)&h23;
            lp.x = *(uint32_t*)&l01; lp.y = *(uint32_t*)&l23;
            *(uint2*)(dAh + r * ROWP + cc) = hp;
            *(uint2*)(dAl + r * ROWP + cc) = lp;
        }
    }

    for (int nt = 0; nt < ntiles; ++nt) {
        int n0 = nt * 64;
        if (tid < 128) red[tid] = 0.f;
        for (int c = 0; c < nch; ++c) {
            __nv_bfloat16* dBh = sB + (2 * c) * SECB;
            __nv_bfloat16* dBl = dBh + SECB;
            int koh = c * 64;
#pragma unroll
            for (int i = 0; i < 2; ++i) {
                int idx = tid + 256 * i;
                int r = idx >> 3, cw = idx & 7;
                const uint4* base = (const uint4*)(B + (size_t)(n0 + r) * ldb);
                uint4 vh = __ldg(base + (koh >> 3) + cw);
                uint4 vl = __ldg(base + ((K + koh) >> 3) + cw);
                *(uint4*)(dBh + r * ROWP + cw * 8) = vh;
                *(uint4*)(dBl + r * ROWP + cw * 8) = vl;
            }
        }
        __syncthreads();

        float acc[2][4][4];
#pragma unroll
        for (int mi = 0; mi < 2; ++mi)
#pragma unroll
            for (int ni = 0; ni < 4; ++ni)
#pragma unroll
                for (int j = 0; j < 4; ++j) acc[mi][ni][j] = 0.f;

        for (int c = 0; c < nch; ++c) {
            uint32_t uAh = uA + (2 * c) * SECA * 2;
            uint32_t uAl = uAh + SECA * 2;
            uint32_t uBh = uB + (2 * c) * SECB * 2;
            uint32_t uBl = uBh + SECB * 2;
            mma_chunk(acc, off, uAh, uAl, uBh, uBl);
        }

#pragma unroll
        for (int ni = 0; ni < 4; ++ni) {
            int colL = wn * 32 + ni * 8 + 2 * t;
            float s0 = 0.f, q0 = 0.f, s1 = 0.f, q1 = 0.f;
#pragma unroll
            for (int mi = 0; mi < 2; ++mi) {
                float* f = acc[mi][ni];
                int row = m0 + wm * 32 + mi * 16 + g;
                if (row < M) {
                    C[(size_t)row * Nc + n0 + colL] = f[0];
                    C[(size_t)row * Nc + n0 + colL + 1] = f[1];
                    s0 += f[0]; q0 += f[0] * f[0];
                    s1 += f[1]; q1 += f[1] * f[1];
                }
                if (row + 8 < M) {
                    C[(size_t)(row + 8) * Nc + n0 + colL] = f[2];
                    C[(size_t)(row + 8) * Nc + n0 + colL + 1] = f[3];
                    s0 += f[2]; q0 += f[2] * f[2];
                    s1 += f[3]; q1 += f[3] * f[3];
                }
            }
#pragma unroll
            for (int off2 = 4; off2 < 32; off2 <<= 1) {
                s0 += __shfl_xor_sync(0xffffffffu, s0, off2);
                q0 += __shfl_xor_sync(0xffffffffu, q0, off2);
                s1 += __shfl_xor_sync(0xffffffffu, s1, off2);
                q1 += __shfl_xor_sync(0xffffffffu, q1, off2);
            }
            if (g == 0) {
                atomicAdd(&red[colL], s0);
                atomicAdd(&red[64 + colL], q0);
                atomicAdd(&red[colL + 1], s1);
                atomicAdd(&red[64 + colL + 1], q1);
            }
        }
        __syncthreads();
        if (tid < 64) {
            atomicAdd(&g_stats[statOff + n0 + tid], (double)red[tid]);
            atomicAdd(&g_stats[statOff + Nc + n0 + tid], (double)red[64 + tid]);
        }
        __syncthreads();
    }
}

// ---------------- final: out = leaky(bn(u2)) + bn(usc), float4 ----------------
__global__ void final_kernel(float4* __restrict__ out, int n4) {
    int i = blockIdx.x * blockDim.x + threadIdx.x;
    if (i >= n4) return;
    int c4 = (i & 63) * 4;
    float4 a = __ldg((const float4*)g_u2 + i);
    float4 s = __ldg((const float4*)g_usc + i);
    float4 o;
#pragma unroll
    for (int j = 0; j < 4; ++j) {
        float2 p2 = __ldg(&g_bnp[128 + c4 + j]);
        float2 ps = __ldg(&g_bnp[384 + c4 + j]);
        float u = fmaf((&a.x)[j], p2.x, p2.y);
        u = (u >= 0.f) ? u : NEG * u;
        (&o.x)[j] = u + fmaf((&s.x)[j], ps.x, ps.y);
    }
    out[i] = o;
}

// ---------------- launch ----------------
extern "C" void kernel_launch(void* const* d_in, const int* in_sizes, int n_in,
                              void* d_out, int out_size) {
    const float* pos    = (const float*)d_in[0];
    const float* x      = (const float*)d_in[1];
    const int*   e_ref  = (const int*)  d_in[2];
    const int*   e_qry  = (const int*)  d_in[3];
    const float* W1     = (const float*)d_in[4];
    const float* g1     = (const float*)d_in[5];
    const float* b1     = (const float*)d_in[6];
    const float* kp     = (const float*)d_in[7];
    const float* Wkp    = (const float*)d_in[8];
    const float* gkp    = (const float*)d_in[9];
    const float* bkp    = (const float*)d_in[10];
    const float* W2     = (const float*)d_in[11];
    const float* g2     = (const float*)d_in[12];
    const float* b2     = (const float*)d_in[13];
    const float* Wsc    = (const float*)d_in[14];
    const float* gsc    = (const float*)d_in[15];
    const float* bsc    = (const float*)d_in[16];
    float* out = (float*)d_out;

    const int M = NPTS;
    const int E = in_sizes[2];

    float *t_p, *u2_p, *usc_p;
    __nv_bfloat16 *Sb_p, *wkpb_p, *w1b_p, *w2b_p, *wscb_p;
    cudaGetSymbolAddress((void**)&t_p,    g_t);
    cudaGetSymbolAddress((void**)&u2_p,   g_u2);
    cudaGetSymbolAddress((void**)&usc_p,  g_usc);
    cudaGetSymbolAddress((void**)&Sb_p,   g_Sb);
    cudaGetSymbolAddress((void**)&w1b_p,  g_w1b);
    cudaGetSymbolAddress((void**)&wkpb_p, g_wkpb);
    cudaGetSymbolAddress((void**)&w2b_p,  g_w2b);
    cudaGetSymbolAddress((void**)&wscb_p, g_wscb);

    cudaFuncSetAttribute(gemm_mma, cudaFuncAttributeMaxDynamicSharedMemorySize, GSMEM_BYTES);
    const int GW_SMEM_K128 = 4 * (SECA + SECB) * 2 + 512;
    const int GW_SMEM_K64  = 2 * (SECA + SECB) * 2 + 512;
    cudaFuncSetAttribute(gemm_wide<1>, cudaFuncAttributeMaxDynamicSharedMemorySize, GW_SMEM_K128);
    cudaFuncSetAttribute(gemm_wide<2>, cudaFuncAttributeMaxDynamicSharedMemorySize, GW_SMEM_K128);

    const int MB = (M + 127) / 128;
    int n4_256 = M * DOUT / 4;

    // 1. zero counters + stats
    zero_kernel<<<(NPTS + 255) / 256, 256>>>();
    // 2. all weight splits (one launch)
    wsplit_all<<<(WSPLIT_TOTAL + 255) / 256, 256>>>(W1, Wkp, W2, Wsc);
    // 3. bin edges by query
    scatter_kernel<<<(E + 255) / 256, 256>>>(e_ref, e_qry, E);
    // 4. t = x @ W1   (fp32 A inline-split; K=128, Nc=64, stats @0)
    gemm_wide<1><<<MB, 256, GW_SMEM_K128>>>(x, w1b_p, t_p, M, DIN, D2, 0, 0);
    // 5. BN params for t
    bn_prep<<<1, 64>>>(0, D2, g1, b1, 0, M);
    // 6. build split-bf16 S (BN+leaky fused)
    sbuild_kernel<<<(M + 7) / 8, 256>>>(pos, kp);
    // 7. y = S @ Wkp  (K=960, Nc=64, stats @128) -> g_t
    gemm_mma<<<dim3(MB, 1), 256, GSMEM_BYTES>>>(Sb_p, wkpb_p, t_p, M, KPTS * D2, D2, 128, D2);
    // 8. BN params for y
    bn_prep<<<1, 64>>>(128, D2, gkp, bkp, 64, M);
    // 9. u2 = leaky(bn(y)) @ W2  (BN+leaky fused into A staging)
    gemm_wide<2><<<MB, 256, GW_SMEM_K64>>>(t_p, w2b_p, u2_p, M, D2, DOUT, 256, 64);
    // 10. usc = x @ Wsc
    gemm_wide<1><<<MB, 256, GW_SMEM_K128>>>(x, wscb_p, usc_p, M, DIN, DOUT, 768, 0);
    // 11. both 256-wide BN preps in one launch
    bn_prep2<<<1, 512>>>(g2, b2, gsc, bsc, M);
    // 12. output
    final_kernel<<<(n4_256 + 255) / 256, 256>>>((float4*)out, n4_256);
}

// round 13
// speedup vs baseline: 1.0638x; 1.0024x over previous
#include <cuda_runtime.h>
#include <cuda_bf16.h>
#include <stdint.h>
#include <math.h>

// ---------------- problem constants ----------------
#define NPTS   100000
#define DIN    128
#define D2     64
#define DOUT   256
#define KPTS   15
#define SIGMA  0.04f
#define NEG    0.1f
#define EPSBN  1e-5f
#define CAP    96

// ---------------- scratch (device globals; no runtime alloc) ----------------
__device__ float  g_t  [(size_t)NPTS * D2];      // fp32 GEMM out (t, then y)
__device__ float  g_u2 [(size_t)NPTS * DOUT];
__device__ float  g_usc[(size_t)NPTS * DOUT];
__device__ __align__(16) __nv_bfloat16 g_Sb [(size_t)NPTS * 2 * KPTS * D2];  // S split
__device__ __align__(16) __nv_bfloat16 g_w1b [D2   * 2 * DIN];   // Bt[n][2K]
__device__ __align__(16) __nv_bfloat16 g_wkpb[D2   * 2 * (KPTS*D2)];
__device__ __align__(16) __nv_bfloat16 g_w2b [DOUT * 2 * D2];
__device__ __align__(16) __nv_bfloat16 g_wscb[DOUT * 2 * DIN];
__device__ int    g_cnt[NPTS];
__device__ int    g_nbr[(size_t)NPTS * CAP];
__device__ double g_stats[1280];   // t:[0,128) y:[128,256) u2:[256,768) usc:[768,1280)
__device__ float2 g_bnp[640];      // (scale,shift): t:[0,64) y:[64,128) u2:[128,384) usc:[384,640)

// ---------------- small kernels ----------------
__global__ void zero_kernel() {
    int i = blockIdx.x * blockDim.x + threadIdx.x;
    if (i < NPTS) g_cnt[i] = 0;
    if (i < 1280) g_stats[i] = 0.0;
}

__global__ void scatter_kernel(const int* __restrict__ e_ref,
                               const int* __restrict__ e_qry, int E) {
    int e = blockIdx.x * blockDim.x + threadIdx.x;
    if (e >= E) return;
    int q = e_qry[e];
    int r = e_ref[e];
    int slot = atomicAdd(&g_cnt[q], 1);
    if (slot < CAP) g_nbr[(size_t)q * CAP + slot] = r;
}

__device__ __forceinline__ void bsplit(float v, __nv_bfloat16& h, __nv_bfloat16& l) {
    h = __float2bfloat16(v);
    l = __float2bfloat16(v - __bfloat162float(h));
}

// one write of one weight element, [K,N] fp32 -> [N,2K] bf16 hi|lo
__device__ __forceinline__ void wsplit_one(const float* W, __nv_bfloat16* out,
                                           int i, int K, int N) {
    int k = i / N, n = i % N;
    __nv_bfloat16 h, l;
    bsplit(W[i], h, l);
    out[(size_t)n * 2 * K + k] = h;
    out[(size_t)n * 2 * K + K + k] = l;
}

#define WSPLIT_TOTAL 118784
__global__ void wsplit_all(const float* __restrict__ W1, const float* __restrict__ Wkp,
                           const float* __restrict__ W2, const float* __restrict__ Wsc) {
    int i = blockIdx.x * blockDim.x + threadIdx.x;
    if (i >= WSPLIT_TOTAL) return;
    if (i < 8192) {
        wsplit_one(W1, g_w1b, i, DIN, D2);
    } else if (i < 69632) {
        wsplit_one(Wkp, g_wkpb, i - 8192, KPTS * D2, D2);
    } else if (i < 86016) {
        wsplit_one(W2, g_w2b, i - 69632, D2, DOUT);
    } else {
        wsplit_one(Wsc, g_wscb, i - 86016, DIN, DOUT);
    }
}

__global__ void bn_prep(int statOff, int C, const float* __restrict__ g,
                        const float* __restrict__ b, int prepOff, int M) {
    int i = threadIdx.x;
    if (i >= C) return;
    double m = g_stats[statOff + i] / (double)M;
    double v = g_stats[statOff + C + i] / (double)M - m * m;
    float rstd = rsqrtf((float)v + EPSBN);
    float scale = g[i] * rstd;
    float shift = b[i] - (float)m * scale;
    g_bnp[prepOff + i] = make_float2(scale, shift);
}

__global__ void bn_prep2(const float* __restrict__ g2, const float* __restrict__ b2,
                         const float* __restrict__ gsc, const float* __restrict__ bsc,
                         int M) {
    int tid = threadIdx.x;
    int i = tid & 255;
    int which = tid >> 8;
    int statOff = which ? 768 : 256;
    int prepOff = which ? 384 : 128;
    const float* g = which ? gsc : g2;
    const float* b = which ? bsc : b2;
    double m = g_stats[statOff + i] / (double)M;
    double v = g_stats[statOff + DOUT + i] / (double)M - m * m;
    float rstd = rsqrtf((float)v + EPSBN);
    float scale = g[i] * rstd;
    float shift = b[i] - (float)m * scale;
    g_bnp[prepOff + i] = make_float2(scale, shift);
}

// ---------------- S build: serial per-warp loop (proven), BN+leaky fused ----------------
__global__ __launch_bounds__(256) void sbuild_kernel(
    const float* __restrict__ pos, const float* __restrict__ kp)
{
    __shared__ float skp[45];
    int tid = threadIdx.x;
    int lane = tid & 31;
    int warp = tid >> 5;
    if (tid < 45) skp[tid] = kp[tid];
    __syncthreads();

    int q = blockIdx.x * 8 + warp;
    if (q >= NPTS) return;

    float kx = 0.f, ky = 0.f, kz = 0.f;
    if (lane < KPTS) {
        kx = skp[lane * 3 + 0];
        ky = skp[lane * 3 + 1];
        kz = skp[lane * 3 + 2];
    }
    float2 p0 = __ldg(&g_bnp[2 * lane]);
    float2 p1 = __ldg(&g_bnp[2 * lane + 1]);

    float a0[KPTS], a1[KPTS];
#pragma unroll
    for (int k = 0; k < KPTS; ++k) { a0[k] = 0.f; a1[k] = 0.f; }

    float4 pq = __ldg((const float4*)pos + q);
    int cnt = g_cnt[q];
    if (cnt > CAP) cnt = CAP;
    const int* nb = g_nbr + (size_t)q * CAP;

    for (int j = 0; j < cnt; ++j) {
        int r = __ldg(&nb[j]);
        float4 pr = __ldg((const float4*)pos + r);
        float rx = pr.y - pq.y;
        float ry = pr.z - pq.z;
        float rz = pr.w - pq.w;
        float infl = 0.f;
        if (lane < KPTS) {
            float dx = rx - kx, dy = ry - ky, dz = rz - kz;
            float d2 = dx * dx + dy * dy + dz * dz;
            if (d2 < SIGMA * SIGMA)
                infl = 1.f - sqrtf(d2) * (1.f / SIGMA);
        }
        unsigned m = __ballot_sync(0xffffffffu, infl > 0.f);
        if (!m) continue;
        float2 hv = __ldg((const float2*)g_t + (size_t)r * 32 + lane);
        float h0 = fmaf(hv.x, p0.x, p0.y);
        h0 = (h0 >= 0.f) ? h0 : NEG * h0;
        float h1 = fmaf(hv.y, p1.x, p1.y);
        h1 = (h1 >= 0.f) ? h1 : NEG * h1;
#pragma unroll
        for (int k = 0; k < KPTS; ++k) {
            if (m & (1u << k)) {
                float w = __shfl_sync(0xffffffffu, infl, k);
                a0[k] += w * h0;
                a1[k] += w * h1;
            }
        }
    }

    __nv_bfloat162* Sout = (__nv_bfloat162*)(g_Sb + (size_t)q * 1920);
#pragma unroll
    for (int k = 0; k < KPTS; ++k) {
        __nv_bfloat16 h0, l0, h1, l1;
        bsplit(a0[k], h0, l0);
        bsplit(a1[k], h1, l1);
        __nv_bfloat162 hh; hh.x = h0; hh.y = h1;
        __nv_bfloat162 ll; ll.x = l0; ll.y = l1;
        Sout[k * 32 + lane] = hh;
        Sout[480 + k * 32 + lane] = ll;
    }
}

// ---------------- MMA / LDSM helpers ----------------
__device__ __forceinline__ void mma16816(float* c, const uint32_t* a, const uint32_t* b) {
    asm volatile(
        "mma.sync.aligned.m16n8k16.row.col.f32.bf16.bf16.f32 "
        "{%0,%1,%2,%3}, {%4,%5,%6,%7}, {%8,%9}, {%0,%1,%2,%3};"
        : "+f"(c[0]), "+f"(c[1]), "+f"(c[2]), "+f"(c[3])
        : "r"(a[0]), "r"(a[1]), "r"(a[2]), "r"(a[3]), "r"(b[0]), "r"(b[1]));
}

#define LDSM4(r, addr) \
    asm volatile("ldmatrix.sync.aligned.m8n8.x4.shared.b16 {%0,%1,%2,%3}, [%4];" \
        : "=r"((r)[0]), "=r"((r)[1]), "=r"((r)[2]), "=r"((r)[3]) : "r"(addr))

#define ROWP 72
#define A_SEC (128 * ROWP)
#define B_SEC (64 * ROWP)
#define GSMEM_BYTES ((2 * A_SEC + 2 * B_SEC) * 2 + 512)   // 55808 B -> 3 CTAs/SM

// lane-dependent LDSM byte offsets (constant across ks/chunks)
struct LdsmOff {
    uint32_t a0, a1, b0, b1;
};
__device__ __forceinline__ LdsmOff ldsm_offsets(int wm, int wn, int lane) {
    LdsmOff o;
    int aRow = wm * 32 + (lane & 15);
    int aCol = ((lane >> 4) & 1) * 8;
    o.a0 = (uint32_t)((aRow * ROWP + aCol) * 2);
    o.a1 = (uint32_t)(((aRow + 16) * ROWP + aCol) * 2);
    int bRow = wn * 32 + (((lane >> 4) & 1) << 3) + (lane & 7);
    int bCol = ((lane >> 3) & 1) * 8;
    o.b0 = (uint32_t)((bRow * ROWP + bCol) * 2);
    o.b1 = (uint32_t)(((bRow + 16) * ROWP + bCol) * 2);
    return o;
}

// inner product step on one staged chunk
__device__ __forceinline__ void mma_chunk(
    float acc[2][4][4], const LdsmOff& o,
    uint32_t uAh, uint32_t uAl, uint32_t uBh, uint32_t uBl)
{
#pragma unroll
    for (int ks = 0; ks < 4; ++ks) {
        uint32_t cb = ks * 32;
        uint32_t ah[2][4], al[2][4], bh[2][4], bl[2][4];
        LDSM4(ah[0], uAh + o.a0 + cb);
        LDSM4(ah[1], uAh + o.a1 + cb);
        LDSM4(al[0], uAl + o.a0 + cb);
        LDSM4(al[1], uAl + o.a1 + cb);
        LDSM4(bh[0], uBh + o.b0 + cb);
        LDSM4(bh[1], uBh + o.b1 + cb);
        LDSM4(bl[0], uBl + o.b0 + cb);
        LDSM4(bl[1], uBl + o.b1 + cb);
#pragma unroll
        for (int mi = 0; mi < 2; ++mi)
#pragma unroll
            for (int ni = 0; ni < 4; ++ni) {
                const uint32_t* pbh = &bh[ni >> 1][(ni & 1) * 2];
                const uint32_t* pbl = &bl[ni >> 1][(ni & 1) * 2];
                mma16816(acc[mi][ni], ah[mi], pbh);
                mma16816(acc[mi][ni], ah[mi], pbl);
                mma16816(acc[mi][ni], al[mi], pbh);
            }
    }
}

// ---------------- unified chunked GEMM: C[M,Nc] = A @ B^T, 64-wide N tile per CTA ----------------
// AMODE 0: A presplit bf16 [M,2K].  AMODE 1: A fp32 [M,K], inline split.
// AMODE 2: A fp32 [M,K], BN(scale,shift)+leaky then split (params at g_bnp[prepOff..]).
// Epilogue: C writes + fused per-column BN stats at g_stats[statOff .. +2*Nc).
template <int AMODE>
__global__ __launch_bounds__(256, 3) void gemm_uni(
    const void* __restrict__ Aptr,
    const __nv_bfloat16* __restrict__ B,
    float* __restrict__ C,
    int M, int K, int Nc, int statOff, int prepOff)
{
    extern __shared__ char smem[];
    __nv_bfloat16* sA = (__nv_bfloat16*)smem;                  // hi @0, lo @A_SEC
    __nv_bfloat16* sB = sA + 2 * A_SEC;                        // hi @0, lo @B_SEC
    float* red = (float*)(smem + (2 * A_SEC + 2 * B_SEC) * 2);

    const int tid = threadIdx.x;
    const int lane = tid & 31;
    const int wid = tid >> 5;
    const int wm = wid & 3;
    const int wn = wid >> 2;
    const int g = lane >> 2;
    const int t = lane & 3;
    const int m0 = blockIdx.x * 128;
    const int n0 = blockIdx.y * 64;
    const int ldb = 2 * K;
    const int nch = K >> 6;

    const LdsmOff off = ldsm_offsets(wm, wn, lane);
    const uint32_t uAh = (uint32_t)__cvta_generic_to_shared(sA);
    const uint32_t uAl = uAh + A_SEC * 2;
    const uint32_t uBh = (uint32_t)__cvta_generic_to_shared(sB);
    const uint32_t uBl = uBh + B_SEC * 2;

    if (tid < 128) red[tid] = 0.f;

    float acc[2][4][4];
#pragma unroll
    for (int mi = 0; mi < 2; ++mi)
#pragma unroll
        for (int ni = 0; ni < 4; ++ni)
#pragma unroll
            for (int j = 0; j < 4; ++j) acc[mi][ni][j] = 0.f;

    for (int c = 0; c < nch; ++c) {
        int koh = c * 64;
        // ---- stage A chunk (128 rows x 64 K-cols, hi+lo) ----
        if (AMODE == 0) {
            const __nv_bfloat16* A = (const __nv_bfloat16*)Aptr;
#pragma unroll
            for (int i = 0; i < 4; ++i) {
                int idx = tid + 256 * i;
                int r = idx >> 3, cw = idx & 7;
                int gr = m0 + r;
                uint4 vh = make_uint4(0, 0, 0, 0), vl = vh;
                if (gr < M) {
                    const uint4* base = (const uint4*)(A + (size_t)gr * ldb);
                    vh = __ldg(base + (koh >> 3) + cw);
                    vl = __ldg(base + ((K + koh) >> 3) + cw);
                }
                *(uint4*)(sA + r * ROWP + cw * 8) = vh;
                *(uint4*)(sA + A_SEC + r * ROWP + cw * 8) = vl;
            }
        } else {
            const float* A32 = (const float*)Aptr;
#pragma unroll
            for (int i = 0; i < 8; ++i) {
                int idx = tid + 256 * i;
                int r = idx >> 4;
                int cc = (idx & 15) * 4;
                int gr = m0 + r;
                float4 v = make_float4(0.f, 0.f, 0.f, 0.f);
                if (gr < M)
                    v = __ldg((const float4*)(A32 + (size_t)gr * K + koh + cc));
                __nv_bfloat16 h[4], l[4];
#pragma unroll
                for (int j = 0; j < 4; ++j) {
                    float u = (&v.x)[j];
                    if (AMODE == 2) {
                        float2 p = __ldg(&g_bnp[prepOff + koh + cc + j]);
                        u = fmaf(u, p.x, p.y);
                        u = (u >= 0.f) ? u : NEG * u;
                    }
                    bsplit(u, h[j], l[j]);
                }
                __nv_bfloat162 h01, h23, l01, l23;
                h01.x = h[0]; h01.y = h[1]; h23.x = h[2]; h23.y = h[3];
                l01.x = l[0]; l01.y = l[1]; l23.x = l[2]; l23.y = l[3];
                uint2 hp, lp;
                hp.x = *(uint32_t*)&h01; hp.y = *(uint32_t*)&h23;
                lp.x = *(uint32_t*)&l01; lp.y = *(uint32_t*)&l23;
                *(uint2*)(sA + r * ROWP + cc) = hp;
                *(uint2*)(sA + A_SEC + r * ROWP + cc) = lp;
            }
        }
        // ---- stage B chunk (64 rows x 64 K-cols, hi+lo) ----
#pragma unroll
        for (int i = 0; i < 2; ++i) {
            int idx = tid + 256 * i;
            int r = idx >> 3, cw = idx & 7;
            const uint4* base = (const uint4*)(B + (size_t)(n0 + r) * ldb);
            uint4 vh = __ldg(base + (koh >> 3) + cw);
            uint4 vl = __ldg(base + ((K + koh) >> 3) + cw);
            *(uint4*)(sB + r * ROWP + cw * 8) = vh;
            *(uint4*)(sB + B_SEC + r * ROWP + cw * 8) = vl;
        }
        __syncthreads();
        mma_chunk(acc, off, uAh, uAl, uBh, uBl);
        __syncthreads();
    }

    // ---- epilogue: C writes + per-column stats ----
#pragma unroll
    for (int ni = 0; ni < 4; ++ni) {
        int colL = wn * 32 + ni * 8 + 2 * t;
        float s0 = 0.f, q0 = 0.f, s1 = 0.f, q1 = 0.f;
#pragma unroll
        for (int mi = 0; mi < 2; ++mi) {
            float* f = acc[mi][ni];
            int row = m0 + wm * 32 + mi * 16 + g;
            if (row < M) {
                C[(size_t)row * Nc + n0 + colL] = f[0];
                C[(size_t)row * Nc + n0 + colL + 1] = f[1];
                s0 += f[0]; q0 += f[0] * f[0];
                s1 += f[1]; q1 += f[1] * f[1];
            }
            if (row + 8 < M) {
                C[(size_t)(row + 8) * Nc + n0 + colL] = f[2];
                C[(size_t)(row + 8) * Nc + n0 + colL + 1] = f[3];
                s0 += f[2]; q0 += f[2] * f[2];
                s1 += f[3]; q1 += f[3] * f[3];
            }
        }
#pragma unroll
        for (int off2 = 4; off2 < 32; off2 <<= 1) {
            s0 += __shfl_xor_sync(0xffffffffu, s0, off2);
            q0 += __shfl_xor_sync(0xffffffffu, q0, off2);
            s1 += __shfl_xor_sync(0xffffffffu, s1, off2);
            q1 += __shfl_xor_sync(0xffffffffu, q1, off2);
        }
        if (g == 0) {
            atomicAdd(&red[colL], s0);
            atomicAdd(&red[64 + colL], q0);
            atomicAdd(&red[colL + 1], s1);
            atomicAdd(&red[64 + colL + 1], q1);
        }
    }
    __syncthreads();
    if (tid < 64) {
        atomicAdd(&g_stats[statOff + n0 + tid], (double)red[tid]);
        atomicAdd(&g_stats[statOff + Nc + n0 + tid], (double)red[64 + tid]);
    }
}

// ---------------- final: out = leaky(bn(u2)) + bn(usc), float4 ----------------
__global__ void final_kernel(float4* __restrict__ out, int n4) {
    int i = blockIdx.x * blockDim.x + threadIdx.x;
    if (i >= n4) return;
    int c4 = (i & 63) * 4;
    float4 a = __ldg((const float4*)g_u2 + i);
    float4 s = __ldg((const float4*)g_usc + i);
    float4 o;
#pragma unroll
    for (int j = 0; j < 4; ++j) {
        float2 p2 = __ldg(&g_bnp[128 + c4 + j]);
        float2 ps = __ldg(&g_bnp[384 + c4 + j]);
        float u = fmaf((&a.x)[j], p2.x, p2.y);
        u = (u >= 0.f) ? u : NEG * u;
        (&o.x)[j] = u + fmaf((&s.x)[j], ps.x, ps.y);
    }
    out[i] = o;
}

// ---------------- launch ----------------
extern "C" void kernel_launch(void* const* d_in, const int* in_sizes, int n_in,
                              void* d_out, int out_size) {
    const float* pos    = (const float*)d_in[0];
    const float* x      = (const float*)d_in[1];
    const int*   e_ref  = (const int*)  d_in[2];
    const int*   e_qry  = (const int*)  d_in[3];
    const float* W1     = (const float*)d_in[4];
    const float* g1     = (const float*)d_in[5];
    const float* b1     = (const float*)d_in[6];
    const float* kp     = (const float*)d_in[7];
    const float* Wkp    = (const float*)d_in[8];
    const float* gkp    = (const float*)d_in[9];
    const float* bkp    = (const float*)d_in[10];
    const float* W2     = (const float*)d_in[11];
    const float* g2     = (const float*)d_in[12];
    const float* b2     = (const float*)d_in[13];
    const float* Wsc    = (const float*)d_in[14];
    const float* gsc    = (const float*)d_in[15];
    const float* bsc    = (const float*)d_in[16];
    float* out = (float*)d_out;

    const int M = NPTS;
    const int E = in_sizes[2];

    float *t_p, *u2_p, *usc_p;
    __nv_bfloat16 *Sb_p, *wkpb_p, *w1b_p, *w2b_p, *wscb_p;
    cudaGetSymbolAddress((void**)&t_p,    g_t);
    cudaGetSymbolAddress((void**)&u2_p,   g_u2);
    cudaGetSymbolAddress((void**)&usc_p,  g_usc);
    cudaGetSymbolAddress((void**)&Sb_p,   g_Sb);
    cudaGetSymbolAddress((void**)&w1b_p,  g_w1b);
    cudaGetSymbolAddress((void**)&wkpb_p, g_wkpb);
    cudaGetSymbolAddress((void**)&w2b_p,  g_w2b);
    cudaGetSymbolAddress((void**)&wscb_p, g_wscb);

    cudaFuncSetAttribute(gemm_uni<0>, cudaFuncAttributeMaxDynamicSharedMemorySize, GSMEM_BYTES);
    cudaFuncSetAttribute(gemm_uni<1>, cudaFuncAttributeMaxDynamicSharedMemorySize, GSMEM_BYTES);
    cudaFuncSetAttribute(gemm_uni<2>, cudaFuncAttributeMaxDynamicSharedMemorySize, GSMEM_BYTES);

    const int MB = (M + 127) / 128;
    int n4_256 = M * DOUT / 4;

    // 1. zero counters + stats
    zero_kernel<<<(NPTS + 255) / 256, 256>>>();
    // 2. all weight splits (one launch)
    wsplit_all<<<(WSPLIT_TOTAL + 255) / 256, 256>>>(W1, Wkp, W2, Wsc);
    // 3. bin edges by query
    scatter_kernel<<<(E + 255) / 256, 256>>>(e_ref, e_qry, E);
    // 4. t = x @ W1   (fp32 A inline-split; K=128, Nc=64, stats @0)
    gemm_uni<1><<<dim3(MB, 1), 256, GSMEM_BYTES>>>(x, w1b_p, t_p, M, DIN, D2, 0, 0);
    // 5. BN params for t
    bn_prep<<<1, 64>>>(0, D2, g1, b1, 0, M);
    // 6. build split-bf16 S (BN+leaky fused)
    sbuild_kernel<<<(M + 7) / 8, 256>>>(pos, kp);
    // 7. y = S @ Wkp  (presplit bf16 A; K=960, Nc=64, stats @128) -> g_t
    gemm_uni<0><<<dim3(MB, 1), 256, GSMEM_BYTES>>>(Sb_p, wkpb_p, t_p, M, KPTS * D2, D2, 128, 0);
    // 8. BN params for y
    bn_prep<<<1, 64>>>(128, D2, gkp, bkp, 64, M);
    // 9. u2 = leaky(bn(y)) @ W2  (fp32 A + BN/leaky inline; K=64, Nc=256, stats @256)
    gemm_uni<2><<<dim3(MB, 4), 256, GSMEM_BYTES>>>(t_p, w2b_p, u2_p, M, D2, DOUT, 256, 64);
    // 10. usc = x @ Wsc  (fp32 A inline-split; K=128, Nc=256, stats @768)
    gemm_uni<1><<<dim3(MB, 4), 256, GSMEM_BYTES>>>(x, wscb_p, usc_p, M, DIN, DOUT, 768, 0);
    // 11. both 256-wide BN preps in one launch
    bn_prep2<<<1, 512>>>(g2, b2, gsc, bsc, M);
    // 12. output
    final_kernel<<<(n4_256 + 255) / 256, 256>>>((float4*)out, n4_256);
}

// round 14
// speedup vs baseline: 1.0788x; 1.0141x over previous
#include <cuda_runtime.h>
#include <cuda_bf16.h>
#include <stdint.h>
#include <math.h>

// ---------------- problem constants ----------------
#define NPTS   100000
#define DIN    128
#define D2     64
#define DOUT   256
#define KPTS   15
#define SIGMA  0.04f
#define NEG    0.1f
#define EPSBN  1e-5f
#define CAP    96

// ---------------- scratch (device globals; no runtime alloc) ----------------
__device__ float  g_t  [(size_t)NPTS * D2];      // fp32 GEMM out (t, then y)
__device__ float  g_u2 [(size_t)NPTS * DOUT];
__device__ float  g_usc[(size_t)NPTS * DOUT];
__device__ __align__(16) __nv_bfloat16 g_Sb [(size_t)NPTS * 2 * KPTS * D2];  // S split
__device__ __align__(16) __nv_bfloat16 g_w1b [D2   * 2 * DIN];   // Bt[n][2K]
__device__ __align__(16) __nv_bfloat16 g_wkpb[D2   * 2 * (KPTS*D2)];
__device__ __align__(16) __nv_bfloat16 g_w2b [DOUT * 2 * D2];
__device__ __align__(16) __nv_bfloat16 g_wscb[DOUT * 2 * DIN];
__device__ int    g_cnt[NPTS];
__device__ int    g_nbr[(size_t)NPTS * CAP];
__device__ double g_stats[1280];   // t:[0,128) y:[128,256) u2:[256,768) usc:[768,1280)
__device__ float2 g_bnp[640];      // (scale,shift): t:[0,64) y:[64,128) u2:[128,384) usc:[384,640)

// ---------------- small kernels ----------------
__global__ void zero_kernel() {
    int i = blockIdx.x * blockDim.x + threadIdx.x;
    if (i < NPTS) g_cnt[i] = 0;
    if (i < 1280) g_stats[i] = 0.0;
}

__global__ void scatter_kernel(const int* __restrict__ e_ref,
                               const int* __restrict__ e_qry, int E) {
    int e = blockIdx.x * blockDim.x + threadIdx.x;
    if (e >= E) return;
    int q = e_qry[e];
    int r = e_ref[e];
    int slot = atomicAdd(&g_cnt[q], 1);
    if (slot < CAP) g_nbr[(size_t)q * CAP + slot] = r;
}

__device__ __forceinline__ void bsplit(float v, __nv_bfloat16& h, __nv_bfloat16& l) {
    h = __float2bfloat16(v);
    l = __float2bfloat16(v - __bfloat162float(h));
}

__device__ __forceinline__ void wsplit_one(const float* W, __nv_bfloat16* out,
                                           int i, int K, int N) {
    int k = i / N, n = i % N;
    __nv_bfloat16 h, l;
    bsplit(W[i], h, l);
    out[(size_t)n * 2 * K + k] = h;
    out[(size_t)n * 2 * K + K + k] = l;
}

#define WSPLIT_TOTAL 118784
__global__ void wsplit_all(const float* __restrict__ W1, const float* __restrict__ Wkp,
                           const float* __restrict__ W2, const float* __restrict__ Wsc) {
    int i = blockIdx.x * blockDim.x + threadIdx.x;
    if (i >= WSPLIT_TOTAL) return;
    if (i < 8192) {
        wsplit_one(W1, g_w1b, i, DIN, D2);
    } else if (i < 69632) {
        wsplit_one(Wkp, g_wkpb, i - 8192, KPTS * D2, D2);
    } else if (i < 86016) {
        wsplit_one(W2, g_w2b, i - 69632, D2, DOUT);
    } else {
        wsplit_one(Wsc, g_wscb, i - 86016, DIN, DOUT);
    }
}

__global__ void bn_prep(int statOff, int C, const float* __restrict__ g,
                        const float* __restrict__ b, int prepOff, int M) {
    int i = threadIdx.x;
    if (i >= C) return;
    double m = g_stats[statOff + i] / (double)M;
    double v = g_stats[statOff + C + i] / (double)M - m * m;
    float rstd = rsqrtf((float)v + EPSBN);
    float scale = g[i] * rstd;
    float shift = b[i] - (float)m * scale;
    g_bnp[prepOff + i] = make_float2(scale, shift);
}

__global__ void bn_prep2(const float* __restrict__ g2, const float* __restrict__ b2,
                         const float* __restrict__ gsc, const float* __restrict__ bsc,
                         int M) {
    int tid = threadIdx.x;
    int i = tid & 255;
    int which = tid >> 8;
    int statOff = which ? 768 : 256;
    int prepOff = which ? 384 : 128;
    const float* g = which ? gsc : g2;
    const float* b = which ? bsc : b2;
    double m = g_stats[statOff + i] / (double)M;
    double v = g_stats[statOff + DOUT + i] / (double)M - m * m;
    float rstd = rsqrtf((float)v + EPSBN);
    float scale = g[i] * rstd;
    float shift = b[i] - (float)m * scale;
    g_bnp[prepOff + i] = make_float2(scale, shift);
}

// ---------------- S build: serial per-warp loop (proven), BN+leaky fused ----------------
__global__ __launch_bounds__(256) void sbuild_kernel(
    const float* __restrict__ pos, const float* __restrict__ kp)
{
    __shared__ float skp[45];
    int tid = threadIdx.x;
    int lane = tid & 31;
    int warp = tid >> 5;
    if (tid < 45) skp[tid] = kp[tid];
    __syncthreads();

    int q = blockIdx.x * 8 + warp;
    if (q >= NPTS) return;

    float kx = 0.f, ky = 0.f, kz = 0.f;
    if (lane < KPTS) {
        kx = skp[lane * 3 + 0];
        ky = skp[lane * 3 + 1];
        kz = skp[lane * 3 + 2];
    }
    float2 p0 = __ldg(&g_bnp[2 * lane]);
    float2 p1 = __ldg(&g_bnp[2 * lane + 1]);

    float a0[KPTS], a1[KPTS];
#pragma unroll
    for (int k = 0; k < KPTS; ++k) { a0[k] = 0.f; a1[k] = 0.f; }

    float4 pq = __ldg((const float4*)pos + q);
    int cnt = g_cnt[q];
    if (cnt > CAP) cnt = CAP;
    const int* nb = g_nbr + (size_t)q * CAP;

    for (int j = 0; j < cnt; ++j) {
        int r = __ldg(&nb[j]);
        float4 pr = __ldg((const float4*)pos + r);
        float rx = pr.y - pq.y;
        float ry = pr.z - pq.z;
        float rz = pr.w - pq.w;
        float infl = 0.f;
        if (lane < KPTS) {
            float dx = rx - kx, dy = ry - ky, dz = rz - kz;
            float d2 = dx * dx + dy * dy + dz * dz;
            if (d2 < SIGMA * SIGMA)
                infl = 1.f - sqrtf(d2) * (1.f / SIGMA);
        }
        unsigned m = __ballot_sync(0xffffffffu, infl > 0.f);
        if (!m) continue;
        float2 hv = __ldg((const float2*)g_t + (size_t)r * 32 + lane);
        float h0 = fmaf(hv.x, p0.x, p0.y);
        h0 = (h0 >= 0.f) ? h0 : NEG * h0;
        float h1 = fmaf(hv.y, p1.x, p1.y);
        h1 = (h1 >= 0.f) ? h1 : NEG * h1;
#pragma unroll
        for (int k = 0; k < KPTS; ++k) {
            if (m & (1u << k)) {
                float w = __shfl_sync(0xffffffffu, infl, k);
                a0[k] += w * h0;
                a1[k] += w * h1;
            }
        }
    }

    __nv_bfloat162* Sout = (__nv_bfloat162*)(g_Sb + (size_t)q * 1920);
#pragma unroll
    for (int k = 0; k < KPTS; ++k) {
        __nv_bfloat16 h0, l0, h1, l1;
        bsplit(a0[k], h0, l0);
        bsplit(a1[k], h1, l1);
        __nv_bfloat162 hh; hh.x = h0; hh.y = h1;
        __nv_bfloat162 ll; ll.x = l0; ll.y = l1;
        Sout[k * 32 + lane] = hh;
        Sout[480 + k * 32 + lane] = ll;
    }
}

// ---------------- MMA / LDSM / cp.async helpers ----------------
__device__ __forceinline__ void mma16816(float* c, const uint32_t* a, const uint32_t* b) {
    asm volatile(
        "mma.sync.aligned.m16n8k16.row.col.f32.bf16.bf16.f32 "
        "{%0,%1,%2,%3}, {%4,%5,%6,%7}, {%8,%9}, {%0,%1,%2,%3};"
        : "+f"(c[0]), "+f"(c[1]), "+f"(c[2]), "+f"(c[3])
        : "r"(a[0]), "r"(a[1]), "r"(a[2]), "r"(a[3]), "r"(b[0]), "r"(b[1]));
}

#define LDSM4(r, addr) \
    asm volatile("ldmatrix.sync.aligned.m8n8.x4.shared.b16 {%0,%1,%2,%3}, [%4];" \
        : "=r"((r)[0]), "=r"((r)[1]), "=r"((r)[2]), "=r"((r)[3]) : "r"(addr))

__device__ __forceinline__ void cp16(uint32_t dst, const void* src, int sz) {
    asm volatile("cp.async.cg.shared.global [%0], [%1], 16, %2;"
                 :: "r"(dst), "l"(src), "r"(sz));
}
#define CP_COMMIT() asm volatile("cp.async.commit_group;" ::: "memory")
#define CP_WAIT0()  asm volatile("cp.async.wait_group 0;" ::: "memory")

#define ROWP 72
#define A_SEC (128 * ROWP)
#define B_SEC (64 * ROWP)
#define STAGE_BYTES ((2 * A_SEC + 2 * B_SEC) * 2)     // 55296
#define GSMEM_BYTES (2 * STAGE_BYTES + 512)           // 111104 -> 2 CTAs/SM

struct LdsmOff {
    uint32_t a0, a1, b0, b1;
};
__device__ __forceinline__ LdsmOff ldsm_offsets(int wm, int wn, int lane) {
    LdsmOff o;
    int aRow = wm * 32 + (lane & 15);
    int aCol = ((lane >> 4) & 1) * 8;
    o.a0 = (uint32_t)((aRow * ROWP + aCol) * 2);
    o.a1 = (uint32_t)(((aRow + 16) * ROWP + aCol) * 2);
    int bRow = wn * 32 + (((lane >> 4) & 1) << 3) + (lane & 7);
    int bCol = ((lane >> 3) & 1) * 8;
    o.b0 = (uint32_t)((bRow * ROWP + bCol) * 2);
    o.b1 = (uint32_t)(((bRow + 16) * ROWP + bCol) * 2);
    return o;
}

__device__ __forceinline__ void mma_chunk(
    float acc[2][4][4], const LdsmOff& o, uint32_t stageBase)
{
    uint32_t uAh = stageBase;
    uint32_t uAl = stageBase + A_SEC * 2;
    uint32_t uBh = stageBase + 4 * A_SEC;          // 2*A_SEC elems * 2B
    uint32_t uBl = uBh + B_SEC * 2;
#pragma unroll
    for (int ks = 0; ks < 4; ++ks) {
        uint32_t cb = ks * 32;
        uint32_t ah[2][4], al[2][4], bh[2][4], bl[2][4];
        LDSM4(ah[0], uAh + o.a0 + cb);
        LDSM4(ah[1], uAh + o.a1 + cb);
        LDSM4(al[0], uAl + o.a0 + cb);
        LDSM4(al[1], uAl + o.a1 + cb);
        LDSM4(bh[0], uBh + o.b0 + cb);
        LDSM4(bh[1], uBh + o.b1 + cb);
        LDSM4(bl[0], uBl + o.b0 + cb);
        LDSM4(bl[1], uBl + o.b1 + cb);
#pragma unroll
        for (int mi = 0; mi < 2; ++mi)
#pragma unroll
            for (int ni = 0; ni < 4; ++ni) {
                const uint32_t* pbh = &bh[ni >> 1][(ni & 1) * 2];
                const uint32_t* pbl = &bl[ni >> 1][(ni & 1) * 2];
                mma16816(acc[mi][ni], ah[mi], pbh);
                mma16816(acc[mi][ni], ah[mi], pbl);
                mma16816(acc[mi][ni], al[mi], pbh);
            }
    }
}

// ---------------- unified pipelined GEMM: C[M,Nc] = A @ B^T, 64-wide N tile per CTA ----------------
// AMODE 0: A presplit bf16 [M,2K] (cp.async).  AMODE 1: A fp32, inline split (regs).
// AMODE 2: A fp32, BN+leaky then split.  B always presplit bf16 [Nc,2K] (cp.async).
template <int AMODE>
__global__ __launch_bounds__(256, 2) void gemm_uni(
    const void* __restrict__ Aptr,
    const __nv_bfloat16* __restrict__ B,
    float* __restrict__ C,
    int M, int K, int Nc, int statOff, int prepOff)
{
    extern __shared__ char smem[];
    float* red = (float*)(smem + 2 * STAGE_BYTES);

    const int tid = threadIdx.x;
    const int lane = tid & 31;
    const int wid = tid >> 5;
    const int wm = wid & 3;
    const int wn = wid >> 2;
    const int g = lane >> 2;
    const int t = lane & 3;
    const int m0 = blockIdx.x * 128;
    const int n0 = blockIdx.y * 64;
    const int ldb = 2 * K;
    const int nch = K >> 6;

    const LdsmOff off = ldsm_offsets(wm, wn, lane);
    const uint32_t uS = (uint32_t)__cvta_generic_to_shared(smem);

    if (tid < 128) red[tid] = 0.f;

    // ---- staging helpers (lambdas over tid) ----
    // A via cp.async (AMODE 0)
    auto stageA_cp = [&](int c, uint32_t base) {
        const __nv_bfloat16* A = (const __nv_bfloat16*)Aptr;
        int koh = c * 64;
#pragma unroll
        for (int i = 0; i < 4; ++i) {
            int idx = tid + 256 * i;
            int r = idx >> 3, cw = idx & 7;
            int gr = m0 + r;
            int sz = (gr < M) ? 16 : 0;
            int gra = (gr < M) ? gr : 0;
            const __nv_bfloat16* sh = A + (size_t)gra * ldb + koh + cw * 8;
            const __nv_bfloat16* sl = sh + K;
            uint32_t d = base + (uint32_t)(r * ROWP + cw * 8) * 2;
            cp16(d, sh, sz);
            cp16(d + A_SEC * 2, sl, sz);
        }
    };
    // B via cp.async (all modes)
    auto stageB_cp = [&](int c, uint32_t base) {
        int koh = c * 64;
#pragma unroll
        for (int i = 0; i < 2; ++i) {
            int idx = tid + 256 * i;
            int r = idx >> 3, cw = idx & 7;
            const __nv_bfloat16* sh = B + (size_t)(n0 + r) * ldb + koh + cw * 8;
            const __nv_bfloat16* sl = sh + K;
            uint32_t d = base + (uint32_t)(4 * A_SEC) + (uint32_t)(r * ROWP + cw * 8) * 2;
            cp16(d, sh, 16);
            cp16(d + B_SEC * 2, sl, 16);
        }
    };
    // A fp32 -> regs (AMODE 1/2)
    float4 av[8];
    auto loadA = [&](int c) {
        const float* A32 = (const float*)Aptr;
        int koh = c * 64;
#pragma unroll
        for (int i = 0; i < 8; ++i) {
            int idx = tid + 256 * i;
            int r = idx >> 4;
            int cc = (idx & 15) * 4;
            int gr = m0 + r;
            av[i] = (gr < M) ? __ldg((const float4*)(A32 + (size_t)gr * K + koh + cc))
                             : make_float4(0.f, 0.f, 0.f, 0.f);
        }
    };
    auto storeA = [&](int c, uint32_t baseOff /*byte offset into smem*/) {
        __nv_bfloat16* sA = (__nv_bfloat16*)(smem + baseOff);
        int koh = c * 64;
#pragma unroll
        for (int i = 0; i < 8; ++i) {
            int idx = tid + 256 * i;
            int r = idx >> 4;
            int cc = (idx & 15) * 4;
            __nv_bfloat16 h[4], l[4];
#pragma unroll
            for (int j = 0; j < 4; ++j) {
                float u = (&av[i].x)[j];
                if (AMODE == 2) {
                    float2 p = __ldg(&g_bnp[prepOff + koh + cc + j]);
                    u = fmaf(u, p.x, p.y);
                    u = (u >= 0.f) ? u : NEG * u;
                }
                bsplit(u, h[j], l[j]);
            }
            __nv_bfloat162 h01, h23, l01, l23;
            h01.x = h[0]; h01.y = h[1]; h23.x = h[2]; h23.y = h[3];
            l01.x = l[0]; l01.y = l[1]; l23.x = l[2]; l23.y = l[3];
            uint2 hp, lp;
            hp.x = *(uint32_t*)&h01; hp.y = *(uint32_t*)&h23;
            lp.x = *(uint32_t*)&l01; lp.y = *(uint32_t*)&l23;
            *(uint2*)(sA + r * ROWP + cc) = hp;
            *(uint2*)(sA + A_SEC + r * ROWP + cc) = lp;
        }
    };

    float acc[2][4][4];
#pragma unroll
    for (int mi = 0; mi < 2; ++mi)
#pragma unroll
        for (int ni = 0; ni < 4; ++ni)
#pragma unroll
            for (int j = 0; j < 4; ++j) acc[mi][ni][j] = 0.f;

    // ---- prologue: stage chunk 0 into buffer 0 ----
    if (AMODE == 0) {
        stageA_cp(0, uS);
    } else {
        loadA(0);
        storeA(0, 0);
    }
    stageB_cp(0, uS);
    CP_COMMIT();

    // ---- pipelined main loop ----
    for (int c = 0; c < nch; ++c) {
        int p = c & 1;
        CP_WAIT0();
        __syncthreads();      // stage p ready; stage p^1 free (prev mma done)
        bool more = (c + 1 < nch);
        if (more) {
            uint32_t nbase = uS + (p ^ 1) * STAGE_BYTES;
            if (AMODE == 0) stageA_cp(c + 1, nbase);
            else            loadA(c + 1);
            stageB_cp(c + 1, nbase);
            CP_COMMIT();
        }
        mma_chunk(acc, off, uS + p * STAGE_BYTES);
        if (more && AMODE != 0)
            storeA(c + 1, (uint32_t)((p ^ 1) * STAGE_BYTES));
    }
    __syncthreads();

    // ---- epilogue: C writes + per-column stats ----
#pragma unroll
    for (int ni = 0; ni < 4; ++ni) {
        int colL = wn * 32 + ni * 8 + 2 * t;
        float s0 = 0.f, q0 = 0.f, s1 = 0.f, q1 = 0.f;
#pragma unroll
        for (int mi = 0; mi < 2; ++mi) {
            float* f = acc[mi][ni];
            int row = m0 + wm * 32 + mi * 16 + g;
            if (row < M) {
                C[(size_t)row * Nc + n0 + colL] = f[0];
                C[(size_t)row * Nc + n0 + colL + 1] = f[1];
                s0 += f[0]; q0 += f[0] * f[0];
                s1 += f[1]; q1 += f[1] * f[1];
            }
            if (row + 8 < M) {
                C[(size_t)(row + 8) * Nc + n0 + colL] = f[2];
                C[(size_t)(row + 8) * Nc + n0 + colL + 1] = f[3];
                s0 += f[2]; q0 += f[2] * f[2];
                s1 += f[3]; q1 += f[3] * f[3];
            }
        }
#pragma unroll
        for (int off2 = 4; off2 < 32; off2 <<= 1) {
            s0 += __shfl_xor_sync(0xffffffffu, s0, off2);
            q0 += __shfl_xor_sync(0xffffffffu, q0, off2);
            s1 += __shfl_xor_sync(0xffffffffu, s1, off2);
            q1 += __shfl_xor_sync(0xffffffffu, q1, off2);
        }
        if (g == 0) {
            atomicAdd(&red[colL], s0);
            atomicAdd(&red[64 + colL], q0);
            atomicAdd(&red[colL + 1], s1);
            atomicAdd(&red[64 + colL + 1], q1);
        }
    }
    __syncthreads();
    if (tid < 64) {
        atomicAdd(&g_stats[statOff + n0 + tid], (double)red[tid]);
        atomicAdd(&g_stats[statOff + Nc + n0 + tid], (double)red[64 + tid]);
    }
}

// ---------------- final: out = leaky(bn(u2)) + bn(usc), float4 ----------------
__global__ void final_kernel(float4* __restrict__ out, int n4) {
    int i = blockIdx.x * blockDim.x + threadIdx.x;
    if (i >= n4) return;
    int c4 = (i & 63) * 4;
    float4 a = __ldg((const float4*)g_u2 + i);
    float4 s = __ldg((const float4*)g_usc + i);
    float4 o;
#pragma unroll
    for (int j = 0; j < 4; ++j) {
        float2 p2 = __ldg(&g_bnp[128 + c4 + j]);
        float2 ps = __ldg(&g_bnp[384 + c4 + j]);
        float u = fmaf((&a.x)[j], p2.x, p2.y);
        u = (u >= 0.f) ? u : NEG * u;
        (&o.x)[j] = u + fmaf((&s.x)[j], ps.x, ps.y);
    }
    out[i] = o;
}

// ---------------- launch ----------------
extern "C" void kernel_launch(void* const* d_in, const int* in_sizes, int n_in,
                              void* d_out, int out_size) {
    const float* pos    = (const float*)d_in[0];
    const float* x      = (const float*)d_in[1];
    const int*   e_ref  = (const int*)  d_in[2];
    const int*   e_qry  = (const int*)  d_in[3];
    const float* W1     = (const float*)d_in[4];
    const float* g1     = (const float*)d_in[5];
    const float* b1     = (const float*)d_in[6];
    const float* kp     = (const float*)d_in[7];
    const float* Wkp    = (const float*)d_in[8];
    const float* gkp    = (const float*)d_in[9];
    const float* bkp    = (const float*)d_in[10];
    const float* W2     = (const float*)d_in[11];
    const float* g2     = (const float*)d_in[12];
    const float* b2     = (const float*)d_in[13];
    const float* Wsc    = (const float*)d_in[14];
    const float* gsc    = (const float*)d_in[15];
    const float* bsc    = (const float*)d_in[16];
    float* out = (float*)d_out;

    const int M = NPTS;
    const int E = in_sizes[2];

    float *t_p, *u2_p, *usc_p;
    __nv_bfloat16 *Sb_p, *wkpb_p, *w1b_p, *w2b_p, *wscb_p;
    cudaGetSymbolAddress((void**)&t_p,    g_t);
    cudaGetSymbolAddress((void**)&u2_p,   g_u2);
    cudaGetSymbolAddress((void**)&usc_p,  g_usc);
    cudaGetSymbolAddress((void**)&Sb_p,   g_Sb);
    cudaGetSymbolAddress((void**)&w1b_p,  g_w1b);
    cudaGetSymbolAddress((void**)&wkpb_p, g_wkpb);
    cudaGetSymbolAddress((void**)&w2b_p,  g_w2b);
    cudaGetSymbolAddress((void**)&wscb_p, g_wscb);

    cudaFuncSetAttribute(gemm_uni<0>, cudaFuncAttributeMaxDynamicSharedMemorySize, GSMEM_BYTES);
    cudaFuncSetAttribute(gemm_uni<1>, cudaFuncAttributeMaxDynamicSharedMemorySize, GSMEM_BYTES);
    cudaFuncSetAttribute(gemm_uni<2>, cudaFuncAttributeMaxDynamicSharedMemorySize, GSMEM_BYTES);

    const int MB = (M + 127) / 128;
    int n4_256 = M * DOUT / 4;

    // 1. zero counters + stats
    zero_kernel<<<(NPTS + 255) / 256, 256>>>();
    // 2. all weight splits (one launch)
    wsplit_all<<<(WSPLIT_TOTAL + 255) / 256, 256>>>(W1, Wkp, W2, Wsc);
    // 3. bin edges by query
    scatter_kernel<<<(E + 255) / 256, 256>>>(e_ref, e_qry, E);
    // 4. t = x @ W1   (fp32 A inline-split; K=128, Nc=64, stats @0)
    gemm_uni<1><<<dim3(MB, 1), 256, GSMEM_BYTES>>>(x, w1b_p, t_p, M, DIN, D2, 0, 0);
    // 5. BN params for t
    bn_prep<<<1, 64>>>(0, D2, g1, b1, 0, M);
    // 6. build split-bf16 S (BN+leaky fused)
    sbuild_kernel<<<(M + 7) / 8, 256>>>(pos, kp);
    // 7. y = S @ Wkp  (presplit bf16 A via cp.async; K=960, Nc=64, stats @128) -> g_t
    gemm_uni<0><<<dim3(MB, 1), 256, GSMEM_BYTES>>>(Sb_p, wkpb_p, t_p, M, KPTS * D2, D2, 128, 0);
    // 8. BN params for y
    bn_prep<<<1, 64>>>(128, D2, gkp, bkp, 64, M);
    // 9. u2 = leaky(bn(y)) @ W2  (fp32 A + BN/leaky inline; K=64, Nc=256, stats @256)
    gemm_uni<2><<<dim3(MB, 4), 256, GSMEM_BYTES>>>(t_p, w2b_p, u2_p, M, D2, DOUT, 256, 64);
    // 10. usc = x @ Wsc  (fp32 A inline-split; K=128, Nc=256, stats @768)
    gemm_uni<1><<<dim3(MB, 4), 256, GSMEM_BYTES>>>(x, wscb_p, usc_p, M, DIN, DOUT, 768, 0);
    // 11. both 256-wide BN preps in one launch
    bn_prep2<<<1, 512>>>(g2, b2, gsc, bsc, M);
    // 12. output
    final_kernel<<<(n4_256 + 255) / 256, 256>>>((float4*)out, n4_256);
}

// round 15
// speedup vs baseline: 1.0951x; 1.0151x over previous
#include <cuda_runtime.h>
#include <cuda_bf16.h>
#include <stdint.h>
#include <math.h>

// ---------------- problem constants ----------------
#define NPTS   100000
#define DIN    128
#define D2     64
#define DOUT   256
#define KPTS   15
#define SIGMA  0.04f
#define NEG    0.1f
#define EPSBN  1e-5f
#define CAP    96

// ---------------- scratch (device globals; no runtime alloc) ----------------
__device__ float  g_t  [(size_t)NPTS * D2];      // fp32 GEMM out (t, then y)
__device__ float  g_u2 [(size_t)NPTS * DOUT];
__device__ float  g_usc[(size_t)NPTS * DOUT];
__device__ __align__(16) __nv_bfloat16 g_Sb [(size_t)NPTS * 2 * KPTS * D2];  // S split
__device__ __align__(16) __nv_bfloat16 g_w1b [D2   * 2 * DIN];   // Bt[n][2K]
__device__ __align__(16) __nv_bfloat16 g_wkpb[D2   * 2 * (KPTS*D2)];
__device__ __align__(16) __nv_bfloat16 g_w2b [DOUT * 2 * D2];
__device__ __align__(16) __nv_bfloat16 g_wscb[DOUT * 2 * DIN];
__device__ int    g_cnt[NPTS];
__device__ int    g_nbr[(size_t)NPTS * CAP];
__device__ double g_stats[1280];   // t:[0,128) y:[128,256) u2:[256,768) usc:[768,1280)
__device__ float2 g_bnp[640];      // (scale,shift): t:[0,64) y:[64,128) u2:[128,384) usc:[384,640)

// ---------------- small kernels ----------------
__global__ void zero_kernel() {
    int i = blockIdx.x * blockDim.x + threadIdx.x;
    if (i < NPTS) g_cnt[i] = 0;
    if (i < 1280) g_stats[i] = 0.0;
}

__global__ void scatter_kernel(const int* __restrict__ e_ref,
                               const int* __restrict__ e_qry, int E) {
    int e = blockIdx.x * blockDim.x + threadIdx.x;
    if (e >= E) return;
    int q = e_qry[e];
    int r = e_ref[e];
    int slot = atomicAdd(&g_cnt[q], 1);
    if (slot < CAP) g_nbr[(size_t)q * CAP + slot] = r;
}

__device__ __forceinline__ void bsplit(float v, __nv_bfloat16& h, __nv_bfloat16& l) {
    h = __float2bfloat16(v);
    l = __float2bfloat16(v - __bfloat162float(h));
}

__device__ __forceinline__ void wsplit_one(const float* W, __nv_bfloat16* out,
                                           int i, int K, int N) {
    int k = i / N, n = i % N;
    __nv_bfloat16 h, l;
    bsplit(W[i], h, l);
    out[(size_t)n * 2 * K + k] = h;
    out[(size_t)n * 2 * K + K + k] = l;
}

#define WSPLIT_TOTAL 118784
__global__ void wsplit_all(const float* __restrict__ W1, const float* __restrict__ Wkp,
                           const float* __restrict__ W2, const float* __restrict__ Wsc) {
    int i = blockIdx.x * blockDim.x + threadIdx.x;
    if (i >= WSPLIT_TOTAL) return;
    if (i < 8192) {
        wsplit_one(W1, g_w1b, i, DIN, D2);
    } else if (i < 69632) {
        wsplit_one(Wkp, g_wkpb, i - 8192, KPTS * D2, D2);
    } else if (i < 86016) {
        wsplit_one(W2, g_w2b, i - 69632, D2, DOUT);
    } else {
        wsplit_one(Wsc, g_wscb, i - 86016, DIN, DOUT);
    }
}

__global__ void bn_prep(int statOff, int C, const float* __restrict__ g,
                        const float* __restrict__ b, int prepOff, int M) {
    int i = threadIdx.x;
    if (i >= C) return;
    double m = g_stats[statOff + i] / (double)M;
    double v = g_stats[statOff + C + i] / (double)M - m * m;
    float rstd = rsqrtf((float)v + EPSBN);
    float scale = g[i] * rstd;
    float shift = b[i] - (float)m * scale;
    g_bnp[prepOff + i] = make_float2(scale, shift);
}

__global__ void bn_prep2(const float* __restrict__ g2, const float* __restrict__ b2,
                         const float* __restrict__ gsc, const float* __restrict__ bsc,
                         int M) {
    int tid = threadIdx.x;
    int i = tid & 255;
    int which = tid >> 8;
    int statOff = which ? 768 : 256;
    int prepOff = which ? 384 : 128;
    const float* g = which ? gsc : g2;
    const float* b = which ? bsc : b2;
    double m = g_stats[statOff + i] / (double)M;
    double v = g_stats[statOff + DOUT + i] / (double)M - m * m;
    float rstd = rsqrtf((float)v + EPSBN);
    float scale = g[i] * rstd;
    float shift = b[i] - (float)m * scale;
    g_bnp[prepOff + i] = make_float2(scale, shift);
}

// ---------------- S build: serial per-warp loop (proven), BN+leaky fused ----------------
__global__ __launch_bounds__(256) void sbuild_kernel(
    const float* __restrict__ pos, const float* __restrict__ kp)
{
    __shared__ float skp[45];
    int tid = threadIdx.x;
    int lane = tid & 31;
    int warp = tid >> 5;
    if (tid < 45) skp[tid] = kp[tid];
    __syncthreads();

    int q = blockIdx.x * 8 + warp;
    if (q >= NPTS) return;

    float kx = 0.f, ky = 0.f, kz = 0.f;
    if (lane < KPTS) {
        kx = skp[lane * 3 + 0];
        ky = skp[lane * 3 + 1];
        kz = skp[lane * 3 + 2];
    }
    float2 p0 = __ldg(&g_bnp[2 * lane]);
    float2 p1 = __ldg(&g_bnp[2 * lane + 1]);

    float a0[KPTS], a1[KPTS];
#pragma unroll
    for (int k = 0; k < KPTS; ++k) { a0[k] = 0.f; a1[k] = 0.f; }

    float4 pq = __ldg((const float4*)pos + q);
    int cnt = g_cnt[q];
    if (cnt > CAP) cnt = CAP;
    const int* nb = g_nbr + (size_t)q * CAP;

    for (int j = 0; j < cnt; ++j) {
        int r = __ldg(&nb[j]);
        float4 pr = __ldg((const float4*)pos + r);
        float rx = pr.y - pq.y;
        float ry = pr.z - pq.z;
        float rz = pr.w - pq.w;
        float infl = 0.f;
        if (lane < KPTS) {
            float dx = rx - kx, dy = ry - ky, dz = rz - kz;
            float d2 = dx * dx + dy * dy + dz * dz;
            if (d2 < SIGMA * SIGMA)
                infl = 1.f - sqrtf(d2) * (1.f / SIGMA);
        }
        unsigned m = __ballot_sync(0xffffffffu, infl > 0.f);
        if (!m) continue;
        float2 hv = __ldg((const float2*)g_t + (size_t)r * 32 + lane);
        float h0 = fmaf(hv.x, p0.x, p0.y);
        h0 = (h0 >= 0.f) ? h0 : NEG * h0;
        float h1 = fmaf(hv.y, p1.x, p1.y);
        h1 = (h1 >= 0.f) ? h1 : NEG * h1;
#pragma unroll
        for (int k = 0; k < KPTS; ++k) {
            if (m & (1u << k)) {
                float w = __shfl_sync(0xffffffffu, infl, k);
                a0[k] += w * h0;
                a1[k] += w * h1;
            }
        }
    }

    __nv_bfloat162* Sout = (__nv_bfloat162*)(g_Sb + (size_t)q * 1920);
#pragma unroll
    for (int k = 0; k < KPTS; ++k) {
        __nv_bfloat16 h0, l0, h1, l1;
        bsplit(a0[k], h0, l0);
        bsplit(a1[k], h1, l1);
        __nv_bfloat162 hh; hh.x = h0; hh.y = h1;
        __nv_bfloat162 ll; ll.x = l0; ll.y = l1;
        Sout[k * 32 + lane] = hh;
        Sout[480 + k * 32 + lane] = ll;
    }
}

// ---------------- MMA / LDSM / cp.async helpers ----------------
__device__ __forceinline__ void mma16816(float* c, const uint32_t* a, const uint32_t* b) {
    asm volatile(
        "mma.sync.aligned.m16n8k16.row.col.f32.bf16.bf16.f32 "
        "{%0,%1,%2,%3}, {%4,%5,%6,%7}, {%8,%9}, {%0,%1,%2,%3};"
        : "+f"(c[0]), "+f"(c[1]), "+f"(c[2]), "+f"(c[3])
        : "r"(a[0]), "r"(a[1]), "r"(a[2]), "r"(a[3]), "r"(b[0]), "r"(b[1]));
}

#define LDSM4(r, addr) \
    asm volatile("ldmatrix.sync.aligned.m8n8.x4.shared.b16 {%0,%1,%2,%3}, [%4];" \
        : "=r"((r)[0]), "=r"((r)[1]), "=r"((r)[2]), "=r"((r)[3]) : "r"(addr))

__device__ __forceinline__ void cp16(uint32_t dst, const void* src, int sz) {
    asm volatile("cp.async.cg.shared.global [%0], [%1], 16, %2;"
                 :: "r"(dst), "l"(src), "r"(sz));
}
#define CP_COMMIT() asm volatile("cp.async.commit_group;" ::: "memory")
#define CP_WAIT0()  asm volatile("cp.async.wait_group 0;" ::: "memory")

// ---- BK=32 tiling: rows padded to 40 bf16 (80 B) ----
#define ROWP 40
#define A_SEC (128 * ROWP)            // bf16 elems per A section (one of hi/lo)
#define B_SEC (64 * ROWP)
#define STAGE_BYTES ((2 * A_SEC + 2 * B_SEC) * 2)     // 30720
#define GSMEM_BYTES (2 * STAGE_BYTES + 512)           // 61952 -> 3 CTAs/SM

struct LdsmOff {
    uint32_t a0, a1, b0, b1;
};
__device__ __forceinline__ LdsmOff ldsm_offsets(int wm, int wn, int lane) {
    LdsmOff o;
    int aRow = wm * 32 + (lane & 15);
    int aCol = ((lane >> 4) & 1) * 8;
    o.a0 = (uint32_t)((aRow * ROWP + aCol) * 2);
    o.a1 = (uint32_t)(((aRow + 16) * ROWP + aCol) * 2);
    int bRow = wn * 32 + (((lane >> 4) & 1) << 3) + (lane & 7);
    int bCol = ((lane >> 3) & 1) * 8;
    o.b0 = (uint32_t)((bRow * ROWP + bCol) * 2);
    o.b1 = (uint32_t)(((bRow + 16) * ROWP + bCol) * 2);
    return o;
}

// one BK=32 chunk: 2 k16 steps
__device__ __forceinline__ void mma_chunk(
    float acc[2][4][4], const LdsmOff& o, uint32_t stageBase)
{
    uint32_t uAh = stageBase;
    uint32_t uAl = stageBase + A_SEC * 2;
    uint32_t uBh = stageBase + 4 * A_SEC;
    uint32_t uBl = uBh + B_SEC * 2;
#pragma unroll
    for (int ks = 0; ks < 2; ++ks) {
        uint32_t cb = ks * 32;
        uint32_t ah[2][4], al[2][4], bh[2][4], bl[2][4];
        LDSM4(ah[0], uAh + o.a0 + cb);
        LDSM4(ah[1], uAh + o.a1 + cb);
        LDSM4(al[0], uAl + o.a0 + cb);
        LDSM4(al[1], uAl + o.a1 + cb);
        LDSM4(bh[0], uBh + o.b0 + cb);
        LDSM4(bh[1], uBh + o.b1 + cb);
        LDSM4(bl[0], uBl + o.b0 + cb);
        LDSM4(bl[1], uBl + o.b1 + cb);
#pragma unroll
        for (int mi = 0; mi < 2; ++mi)
#pragma unroll
            for (int ni = 0; ni < 4; ++ni) {
                const uint32_t* pbh = &bh[ni >> 1][(ni & 1) * 2];
                const uint32_t* pbl = &bl[ni >> 1][(ni & 1) * 2];
                mma16816(acc[mi][ni], ah[mi], pbh);
                mma16816(acc[mi][ni], ah[mi], pbl);
                mma16816(acc[mi][ni], al[mi], pbh);
            }
    }
}

// ---------------- unified pipelined GEMM: C[M,Nc] = A @ B^T, 64-wide N tile per CTA ----------------
// AMODE 0: A presplit bf16 [M,2K] (cp.async).  AMODE 1: A fp32, inline split (regs).
// AMODE 2: A fp32, BN+leaky then split.  B always presplit bf16 [Nc,2K] (cp.async).
template <int AMODE>
__global__ __launch_bounds__(256, 3) void gemm_uni(
    const void* __restrict__ Aptr,
    const __nv_bfloat16* __restrict__ B,
    float* __restrict__ C,
    int M, int K, int Nc, int statOff, int prepOff)
{
    extern __shared__ char smem[];
    float* red = (float*)(smem + 2 * STAGE_BYTES);

    const int tid = threadIdx.x;
    const int lane = tid & 31;
    const int wid = tid >> 5;
    const int wm = wid & 3;
    const int wn = wid >> 2;
    const int g = lane >> 2;
    const int t = lane & 3;
    const int m0 = blockIdx.x * 128;
    const int n0 = blockIdx.y * 64;
    const int ldb = 2 * K;
    const int nch = K >> 5;

    const LdsmOff off = ldsm_offsets(wm, wn, lane);
    const uint32_t uS = (uint32_t)__cvta_generic_to_shared(smem);

    if (tid < 128) red[tid] = 0.f;

    // A via cp.async (AMODE 0): 128 rows x 32 cols per section, 4 x 16B units/row
    auto stageA_cp = [&](int c, uint32_t base) {
        const __nv_bfloat16* A = (const __nv_bfloat16*)Aptr;
        int koh = c * 32;
#pragma unroll
        for (int i = 0; i < 2; ++i) {
            int idx = tid + 256 * i;          // [0,512)
            int r = idx >> 2, cw = idx & 3;
            int gr = m0 + r;
            int sz = (gr < M) ? 16 : 0;
            int gra = (gr < M) ? gr : 0;
            const __nv_bfloat16* sh = A + (size_t)gra * ldb + koh + cw * 8;
            const __nv_bfloat16* sl = sh + K;
            uint32_t d = base + (uint32_t)(r * ROWP + cw * 8) * 2;
            cp16(d, sh, sz);
            cp16(d + A_SEC * 2, sl, sz);
        }
    };
    // B via cp.async: 64 rows x 32 cols per section -> 256 16B units
    auto stageB_cp = [&](int c, uint32_t base) {
        int koh = c * 32;
        if (tid < 256) {
            int r = tid >> 2, cw = tid & 3;
            const __nv_bfloat16* sh = B + (size_t)(n0 + r) * ldb + koh + cw * 8;
            const __nv_bfloat16* sl = sh + K;
            uint32_t d = base + (uint32_t)(4 * A_SEC) + (uint32_t)(r * ROWP + cw * 8) * 2;
            cp16(d, sh, 16);
            cp16(d + B_SEC * 2, sl, 16);
        }
    };
    // A fp32 -> regs (AMODE 1/2): 128x32 fp32 = 4096 floats -> 16/thread
    float4 av[4];
    auto loadA = [&](int c) {
        const float* A32 = (const float*)Aptr;
        int koh = c * 32;
#pragma unroll
        for (int i = 0; i < 4; ++i) {
            int idx = tid + 256 * i;          // [0,1024) quad positions
            int r = idx >> 3;
            int cc = (idx & 7) * 4;
            int gr = m0 + r;
            av[i] = (gr < M) ? __ldg((const float4*)(A32 + (size_t)gr * K + koh + cc))
                             : make_float4(0.f, 0.f, 0.f, 0.f);
        }
    };
    auto storeA = [&](int c, uint32_t baseOff) {
        __nv_bfloat16* sA = (__nv_bfloat16*)(smem + baseOff);
        int koh = c * 32;
#pragma unroll
        for (int i = 0; i < 4; ++i) {
            int idx = tid + 256 * i;
            int r = idx >> 3;
            int cc = (idx & 7) * 4;
            __nv_bfloat16 h[4], l[4];
#pragma unroll
            for (int j = 0; j < 4; ++j) {
                float u = (&av[i].x)[j];
                if (AMODE == 2) {
                    float2 p = __ldg(&g_bnp[prepOff + koh + cc + j]);
                    u = fmaf(u, p.x, p.y);
                    u = (u >= 0.f) ? u : NEG * u;
                }
                bsplit(u, h[j], l[j]);
            }
            __nv_bfloat162 h01, h23, l01, l23;
            h01.x = h[0]; h01.y = h[1]; h23.x = h[2]; h23.y = h[3];
            l01.x = l[0]; l01.y = l[1]; l23.x = l[2]; l23.y = l[3];
            uint2 hp, lp;
            hp.x = *(uint32_t*)&h01; hp.y = *(uint32_t*)&h23;
            lp.x = *(uint32_t*)&l01; lp.y = *(uint32_t*)&l23;
            *(uint2*)(sA + r * ROWP + cc) = hp;
            *(uint2*)(sA + A_SEC + r * ROWP + cc) = lp;
        }
    };

    float acc[2][4][4];
#pragma unroll
    for (int mi = 0; mi < 2; ++mi)
#pragma unroll
        for (int ni = 0; ni < 4; ++ni)
#pragma unroll
            for (int j = 0; j < 4; ++j) acc[mi][ni][j] = 0.f;

    // prologue: stage chunk 0 into buffer 0
    if (AMODE == 0) {
        stageA_cp(0, uS);
    } else {
        loadA(0);
        storeA(0, 0);
    }
    stageB_cp(0, uS);
    CP_COMMIT();

    // pipelined main loop
    for (int c = 0; c < nch; ++c) {
        int p = c & 1;
        CP_WAIT0();
        __syncthreads();
        bool more = (c + 1 < nch);
        if (more) {
            uint32_t nbase = uS + (p ^ 1) * STAGE_BYTES;
            if (AMODE == 0) stageA_cp(c + 1, nbase);
            else            loadA(c + 1);
            stageB_cp(c + 1, nbase);
            CP_COMMIT();
        }
        mma_chunk(acc, off, uS + p * STAGE_BYTES);
        if (more && AMODE != 0)
            storeA(c + 1, (uint32_t)((p ^ 1) * STAGE_BYTES));
    }
    __syncthreads();

    // epilogue: C writes + per-column stats
#pragma unroll
    for (int ni = 0; ni < 4; ++ni) {
        int colL = wn * 32 + ni * 8 + 2 * t;
        float s0 = 0.f, q0 = 0.f, s1 = 0.f, q1 = 0.f;
#pragma unroll
        for (int mi = 0; mi < 2; ++mi) {
            float* f = acc[mi][ni];
            int row = m0 + wm * 32 + mi * 16 + g;
            if (row < M) {
                C[(size_t)row * Nc + n0 + colL] = f[0];
                C[(size_t)row * Nc + n0 + colL + 1] = f[1];
                s0 += f[0]; q0 += f[0] * f[0];
                s1 += f[1]; q1 += f[1] * f[1];
            }
            if (row + 8 < M) {
                C[(size_t)(row + 8) * Nc + n0 + colL] = f[2];
                C[(size_t)(row + 8) * Nc + n0 + colL + 1] = f[3];
                s0 += f[2]; q0 += f[2] * f[2];
                s1 += f[3]; q1 += f[3] * f[3];
            }
        }
#pragma unroll
        for (int off2 = 4; off2 < 32; off2 <<= 1) {
            s0 += __shfl_xor_sync(0xffffffffu, s0, off2);
            q0 += __shfl_xor_sync(0xffffffffu, q0, off2);
            s1 += __shfl_xor_sync(0xffffffffu, s1, off2);
            q1 += __shfl_xor_sync(0xffffffffu, q1, off2);
        }
        if (g == 0) {
            atomicAdd(&red[colL], s0);
            atomicAdd(&red[64 + colL], q0);
            atomicAdd(&red[colL + 1], s1);
            atomicAdd(&red[64 + colL + 1], q1);
        }
    }
    __syncthreads();
    if (tid < 64) {
        atomicAdd(&g_stats[statOff + n0 + tid], (double)red[tid]);
        atomicAdd(&g_stats[statOff + Nc + n0 + tid], (double)red[64 + tid]);
    }
}

// ---------------- final: out = leaky(bn(u2)) + bn(usc), float4 ----------------
__global__ void final_kernel(float4* __restrict__ out, int n4) {
    int i = blockIdx.x * blockDim.x + threadIdx.x;
    if (i >= n4) return;
    int c4 = (i & 63) * 4;
    float4 a = __ldg((const float4*)g_u2 + i);
    float4 s = __ldg((const float4*)g_usc + i);
    float4 o;
#pragma unroll
    for (int j = 0; j < 4; ++j) {
        float2 p2 = __ldg(&g_bnp[128 + c4 + j]);
        float2 ps = __ldg(&g_bnp[384 + c4 + j]);
        float u = fmaf((&a.x)[j], p2.x, p2.y);
        u = (u >= 0.f) ? u : NEG * u;
        (&o.x)[j] = u + fmaf((&s.x)[j], ps.x, ps.y);
    }
    out[i] = o;
}

// ---------------- launch ----------------
extern "C" void kernel_launch(void* const* d_in, const int* in_sizes, int n_in,
                              void* d_out, int out_size) {
    const float* pos    = (const float*)d_in[0];
    const float* x      = (const float*)d_in[1];
    const int*   e_ref  = (const int*)  d_in[2];
    const int*   e_qry  = (const int*)  d_in[3];
    const float* W1     = (const float*)d_in[4];
    const float* g1     = (const float*)d_in[5];
    const float* b1     = (const float*)d_in[6];
    const float* kp     = (const float*)d_in[7];
    const float* Wkp    = (const float*)d_in[8];
    const float* gkp    = (const float*)d_in[9];
    const float* bkp    = (const float*)d_in[10];
    const float* W2     = (const float*)d_in[11];
    const float* g2     = (const float*)d_in[12];
    const float* b2     = (const float*)d_in[13];
    const float* Wsc    = (const float*)d_in[14];
    const float* gsc    = (const float*)d_in[15];
    const float* bsc    = (const float*)d_in[16];
    float* out = (float*)d_out;

    const int M = NPTS;
    const int E = in_sizes[2];

    float *t_p, *u2_p, *usc_p;
    __nv_bfloat16 *Sb_p, *wkpb_p, *w1b_p, *w2b_p, *wscb_p;
    cudaGetSymbolAddress((void**)&t_p,    g_t);
    cudaGetSymbolAddress((void**)&u2_p,   g_u2);
    cudaGetSymbolAddress((void**)&usc_p,  g_usc);
    cudaGetSymbolAddress((void**)&Sb_p,   g_Sb);
    cudaGetSymbolAddress((void**)&w1b_p,  g_w1b);
    cudaGetSymbolAddress((void**)&wkpb_p, g_wkpb);
    cudaGetSymbolAddress((void**)&w2b_p,  g_w2b);
    cudaGetSymbolAddress((void**)&wscb_p, g_wscb);

    cudaFuncSetAttribute(gemm_uni<0>, cudaFuncAttributeMaxDynamicSharedMemorySize, GSMEM_BYTES);
    cudaFuncSetAttribute(gemm_uni<1>, cudaFuncAttributeMaxDynamicSharedMemorySize, GSMEM_BYTES);
    cudaFuncSetAttribute(gemm_uni<2>, cudaFuncAttributeMaxDynamicSharedMemorySize, GSMEM_BYTES);

    const int MB = (M + 127) / 128;
    int n4_256 = M * DOUT / 4;

    // 1. zero counters + stats
    zero_kernel<<<(NPTS + 255) / 256, 256>>>();
    // 2. all weight splits (one launch)
    wsplit_all<<<(WSPLIT_TOTAL + 255) / 256, 256>>>(W1, Wkp, W2, Wsc);
    // 3. bin edges by query
    scatter_kernel<<<(E + 255) / 256, 256>>>(e_ref, e_qry, E);
    // 4. t = x @ W1   (fp32 A inline-split; K=128, Nc=64, stats @0)
    gemm_uni<1><<<dim3(MB, 1), 256, GSMEM_BYTES>>>(x, w1b_p, t_p, M, DIN, D2, 0, 0);
    // 5. BN params for t
    bn_prep<<<1, 64>>>(0, D2, g1, b1, 0, M);
    // 6. build split-bf16 S (BN+leaky fused)
    sbuild_kernel<<<(M + 7) / 8, 256>>>(pos, kp);
    // 7. y = S @ Wkp  (presplit bf16 A via cp.async; K=960, Nc=64, stats @128) -> g_t
    gemm_uni<0><<<dim3(MB, 1), 256, GSMEM_BYTES>>>(Sb_p, wkpb_p, t_p, M, KPTS * D2, D2, 128, 0);
    // 8. BN params for y
    bn_prep<<<1, 64>>>(128, D2, gkp, bkp, 64, M);
    // 9. u2 = leaky(bn(y)) @ W2  (fp32 A + BN/leaky inline; K=64, Nc=256, stats @256)
    gemm_uni<2><<<dim3(MB, 4), 256, GSMEM_BYTES>>>(t_p, w2b_p, u2_p, M, D2, DOUT, 256, 64);
    // 10. usc = x @ Wsc  (fp32 A inline-split; K=128, Nc=256, stats @768)
    gemm_uni<1><<<dim3(MB, 4), 256, GSMEM_BYTES>>>(x, wscb_p, usc_p, M, DIN, DOUT, 768, 0);
    // 11. both 256-wide BN preps in one launch
    bn_prep2<<<1, 512>>>(g2, b2, gsc, bsc, M);
    // 12. output
    final_kernel<<<(n4_256 + 255) / 256, 256>>>((float4*)out, n4_256);
}

// round 16
// speedup vs baseline: 1.1148x; 1.0180x over previous
#include <cuda_runtime.h>
#include <cuda_bf16.h>
#include <stdint.h>
#include <math.h>

// ---------------- problem constants ----------------
#define NPTS   100000
#define DIN    128
#define D2     64
#define DOUT   256
#define KPTS   15
#define SIGMA  0.04f
#define NEG    0.1f
#define EPSBN  1e-5f
#define CAP    96

// ---------------- scratch (device globals; no runtime alloc) ----------------
__device__ float  g_t  [(size_t)NPTS * D2];      // fp32 GEMM out (t, then y)
__device__ float  g_u2 [(size_t)NPTS * DOUT];
__device__ float  g_usc[(size_t)NPTS * DOUT];
__device__ __align__(16) __nv_bfloat16 g_Sb [(size_t)NPTS * 2 * KPTS * D2];  // S split
__device__ __align__(16) __nv_bfloat16 g_w1b [D2   * 2 * DIN];   // Bt[n][2K]
__device__ __align__(16) __nv_bfloat16 g_wkpb[D2   * 2 * (KPTS*D2)];
__device__ __align__(16) __nv_bfloat16 g_w2b [DOUT * 2 * D2];
__device__ __align__(16) __nv_bfloat16 g_wscb[DOUT * 2 * DIN];
__device__ int    g_cnt[NPTS];
__device__ int    g_nbr[(size_t)NPTS * CAP];
__device__ double g_stats[1280];   // t:[0,128) y:[128,256) u2:[256,768) usc:[768,1280)
__device__ float2 g_bnp[640];      // (scale,shift): t:[0,64) y:[64,128) u2:[128,384) usc:[384,640)

// ---------------- small kernels ----------------
__global__ void zero_kernel() {
    int i = blockIdx.x * blockDim.x + threadIdx.x;
    if (i < NPTS) g_cnt[i] = 0;
    if (i < 1280) g_stats[i] = 0.0;
}

__global__ void scatter_kernel(const int* __restrict__ e_ref,
                               const int* __restrict__ e_qry, int E) {
    int e = blockIdx.x * blockDim.x + threadIdx.x;
    if (e >= E) return;
    int q = e_qry[e];
    int r = e_ref[e];
    int slot = atomicAdd(&g_cnt[q], 1);
    if (slot < CAP) g_nbr[(size_t)q * CAP + slot] = r;
}

__device__ __forceinline__ void bsplit(float v, __nv_bfloat16& h, __nv_bfloat16& l) {
    h = __float2bfloat16(v);
    l = __float2bfloat16(v - __bfloat162float(h));
}

__device__ __forceinline__ void wsplit_one(const float* W, __nv_bfloat16* out,
                                           int i, int K, int N) {
    int k = i / N, n = i % N;
    __nv_bfloat16 h, l;
    bsplit(W[i], h, l);
    out[(size_t)n * 2 * K + k] = h;
    out[(size_t)n * 2 * K + K + k] = l;
}

#define WSPLIT_TOTAL 118784
__global__ void wsplit_all(const float* __restrict__ W1, const float* __restrict__ Wkp,
                           const float* __restrict__ W2, const float* __restrict__ Wsc) {
    int i = blockIdx.x * blockDim.x + threadIdx.x;
    if (i >= WSPLIT_TOTAL) return;
    if (i < 8192) {
        wsplit_one(W1, g_w1b, i, DIN, D2);
    } else if (i < 69632) {
        wsplit_one(Wkp, g_wkpb, i - 8192, KPTS * D2, D2);
    } else if (i < 86016) {
        wsplit_one(W2, g_w2b, i - 69632, D2, DOUT);
    } else {
        wsplit_one(Wsc, g_wscb, i - 86016, DIN, DOUT);
    }
}

__global__ void bn_prep(int statOff, int C, const float* __restrict__ g,
                        const float* __restrict__ b, int prepOff, int M) {
    int i = threadIdx.x;
    if (i >= C) return;
    double m = g_stats[statOff + i] / (double)M;
    double v = g_stats[statOff + C + i] / (double)M - m * m;
    float rstd = rsqrtf((float)v + EPSBN);
    float scale = g[i] * rstd;
    float shift = b[i] - (float)m * scale;
    g_bnp[prepOff + i] = make_float2(scale, shift);
}

__global__ void bn_prep2(const float* __restrict__ g2, const float* __restrict__ b2,
                         const float* __restrict__ gsc, const float* __restrict__ bsc,
                         int M) {
    int tid = threadIdx.x;
    int i = tid & 255;
    int which = tid >> 8;
    int statOff = which ? 768 : 256;
    int prepOff = which ? 384 : 128;
    const float* g = which ? gsc : g2;
    const float* b = which ? bsc : b2;
    double m = g_stats[statOff + i] / (double)M;
    double v = g_stats[statOff + DOUT + i] / (double)M - m * m;
    float rstd = rsqrtf((float)v + EPSBN);
    float scale = g[i] * rstd;
    float shift = b[i] - (float)m * scale;
    g_bnp[prepOff + i] = make_float2(scale, shift);
}

// ---------------- S build: serial per-warp loop (proven), BN+leaky fused ----------------
__global__ __launch_bounds__(256) void sbuild_kernel(
    const float* __restrict__ pos, const float* __restrict__ kp)
{
    __shared__ float skp[45];
    int tid = threadIdx.x;
    int lane = tid & 31;
    int warp = tid >> 5;
    if (tid < 45) skp[tid] = kp[tid];
    __syncthreads();

    int q = blockIdx.x * 8 + warp;
    if (q >= NPTS) return;

    float kx = 0.f, ky = 0.f, kz = 0.f;
    if (lane < KPTS) {
        kx = skp[lane * 3 + 0];
        ky = skp[lane * 3 + 1];
        kz = skp[lane * 3 + 2];
    }
    float2 p0 = __ldg(&g_bnp[2 * lane]);
    float2 p1 = __ldg(&g_bnp[2 * lane + 1]);

    float a0[KPTS], a1[KPTS];
#pragma unroll
    for (int k = 0; k < KPTS; ++k) { a0[k] = 0.f; a1[k] = 0.f; }

    float4 pq = __ldg((const float4*)pos + q);
    int cnt = g_cnt[q];
    if (cnt > CAP) cnt = CAP;
    const int* nb = g_nbr + (size_t)q * CAP;

    for (int j = 0; j < cnt; ++j) {
        int r = __ldg(&nb[j]);
        float4 pr = __ldg((const float4*)pos + r);
        float rx = pr.y - pq.y;
        float ry = pr.z - pq.z;
        float rz = pr.w - pq.w;
        float infl = 0.f;
        if (lane < KPTS) {
            float dx = rx - kx, dy = ry - ky, dz = rz - kz;
            float d2 = dx * dx + dy * dy + dz * dz;
            if (d2 < SIGMA * SIGMA)
                infl = 1.f - sqrtf(d2) * (1.f / SIGMA);
        }
        unsigned m = __ballot_sync(0xffffffffu, infl > 0.f);
        if (!m) continue;
        float2 hv = __ldg((const float2*)g_t + (size_t)r * 32 + lane);
        float h0 = fmaf(hv.x, p0.x, p0.y);
        h0 = (h0 >= 0.f) ? h0 : NEG * h0;
        float h1 = fmaf(hv.y, p1.x, p1.y);
        h1 = (h1 >= 0.f) ? h1 : NEG * h1;
#pragma unroll
        for (int k = 0; k < KPTS; ++k) {
            if (m & (1u << k)) {
                float w = __shfl_sync(0xffffffffu, infl, k);
                a0[k] += w * h0;
                a1[k] += w * h1;
            }
        }
    }

    __nv_bfloat162* Sout = (__nv_bfloat162*)(g_Sb + (size_t)q * 1920);
#pragma unroll
    for (int k = 0; k < KPTS; ++k) {
        __nv_bfloat16 h0, l0, h1, l1;
        bsplit(a0[k], h0, l0);
        bsplit(a1[k], h1, l1);
        __nv_bfloat162 hh; hh.x = h0; hh.y = h1;
        __nv_bfloat162 ll; ll.x = l0; ll.y = l1;
        Sout[k * 32 + lane] = hh;
        Sout[480 + k * 32 + lane] = ll;
    }
}

// ---------------- MMA / LDSM / cp.async helpers ----------------
__device__ __forceinline__ void mma16816(float* c, const uint32_t* a, const uint32_t* b) {
    asm volatile(
        "mma.sync.aligned.m16n8k16.row.col.f32.bf16.bf16.f32 "
        "{%0,%1,%2,%3}, {%4,%5,%6,%7}, {%8,%9}, {%0,%1,%2,%3};"
        : "+f"(c[0]), "+f"(c[1]), "+f"(c[2]), "+f"(c[3])
        : "r"(a[0]), "r"(a[1]), "r"(a[2]), "r"(a[3]), "r"(b[0]), "r"(b[1]));
}

#define LDSM4(r, addr) \
    asm volatile("ldmatrix.sync.aligned.m8n8.x4.shared.b16 {%0,%1,%2,%3}, [%4];" \
        : "=r"((r)[0]), "=r"((r)[1]), "=r"((r)[2]), "=r"((r)[3]) : "r"(addr))

__device__ __forceinline__ void cp16(uint32_t dst, const void* src, int sz) {
    asm volatile("cp.async.cg.shared.global [%0], [%1], 16, %2;"
                 :: "r"(dst), "l"(src), "r"(sz));
}
#define CP_COMMIT() asm volatile("cp.async.commit_group;" ::: "memory")
#define CP_WAIT0()  asm volatile("cp.async.wait_group 0;" ::: "memory")

// ---- BK=32 tiling: rows padded to 40 bf16 (80 B) ----
#define ROWP 40
#define A_SEC (128 * ROWP)
#define B_SEC (64 * ROWP)
#define STAGE_BYTES ((2 * A_SEC + 2 * B_SEC) * 2)     // 30720
#define GSMEM_BYTES (2 * STAGE_BYTES + 512)           // 61952 -> 3 CTAs/SM

struct LdsmOff {
    uint32_t a0, a1, b0, b1;
};
__device__ __forceinline__ LdsmOff ldsm_offsets(int wm, int wn, int lane) {
    LdsmOff o;
    int aRow = wm * 32 + (lane & 15);
    int aCol = ((lane >> 4) & 1) * 8;
    o.a0 = (uint32_t)((aRow * ROWP + aCol) * 2);
    o.a1 = (uint32_t)(((aRow + 16) * ROWP + aCol) * 2);
    int bRow = wn * 32 + (((lane >> 4) & 1) << 3) + (lane & 7);
    int bCol = ((lane >> 3) & 1) * 8;
    o.b0 = (uint32_t)((bRow * ROWP + bCol) * 2);
    o.b1 = (uint32_t)(((bRow + 16) * ROWP + bCol) * 2);
    return o;
}

__device__ __forceinline__ void mma_chunk(
    float acc[2][4][4], const LdsmOff& o, uint32_t stageBase)
{
    uint32_t uAh = stageBase;
    uint32_t uAl = stageBase + A_SEC * 2;
    uint32_t uBh = stageBase + 4 * A_SEC;
    uint32_t uBl = uBh + B_SEC * 2;
#pragma unroll
    for (int ks = 0; ks < 2; ++ks) {
        uint32_t cb = ks * 32;
        uint32_t ah[2][4], al[2][4], bh[2][4], bl[2][4];
        LDSM4(ah[0], uAh + o.a0 + cb);
        LDSM4(ah[1], uAh + o.a1 + cb);
        LDSM4(al[0], uAl + o.a0 + cb);
        LDSM4(al[1], uAl + o.a1 + cb);
        LDSM4(bh[0], uBh + o.b0 + cb);
        LDSM4(bh[1], uBh + o.b1 + cb);
        LDSM4(bl[0], uBl + o.b0 + cb);
        LDSM4(bl[1], uBl + o.b1 + cb);
#pragma unroll
        for (int mi = 0; mi < 2; ++mi)
#pragma unroll
            for (int ni = 0; ni < 4; ++ni) {
                const uint32_t* pbh = &bh[ni >> 1][(ni & 1) * 2];
                const uint32_t* pbl = &bl[ni >> 1][(ni & 1) * 2];
                mma16816(acc[mi][ni], ah[mi], pbh);
                mma16816(acc[mi][ni], ah[mi], pbl);
                mma16816(acc[mi][ni], al[mi], pbh);
            }
    }
}

// ---------------- unified pipelined GEMM (identical to round 15) ----------------
template <int AMODE>
__global__ __launch_bounds__(256, 3) void gemm_uni(
    const void* __restrict__ Aptr,
    const __nv_bfloat16* __restrict__ B,
    float* __restrict__ C,
    int M, int K, int Nc, int statOff, int prepOff)
{
    extern __shared__ char smem[];
    float* red = (float*)(smem + 2 * STAGE_BYTES);

    const int tid = threadIdx.x;
    const int lane = tid & 31;
    const int wid = tid >> 5;
    const int wm = wid & 3;
    const int wn = wid >> 2;
    const int g = lane >> 2;
    const int t = lane & 3;
    const int m0 = blockIdx.x * 128;
    const int n0 = blockIdx.y * 64;
    const int ldb = 2 * K;
    const int nch = K >> 5;

    const LdsmOff off = ldsm_offsets(wm, wn, lane);
    const uint32_t uS = (uint32_t)__cvta_generic_to_shared(smem);

    if (tid < 128) red[tid] = 0.f;

    auto stageA_cp = [&](int c, uint32_t base) {
        const __nv_bfloat16* A = (const __nv_bfloat16*)Aptr;
        int koh = c * 32;
#pragma unroll
        for (int i = 0; i < 2; ++i) {
            int idx = tid + 256 * i;
            int r = idx >> 2, cw = idx & 3;
            int gr = m0 + r;
            int sz = (gr < M) ? 16 : 0;
            int gra = (gr < M) ? gr : 0;
            const __nv_bfloat16* sh = A + (size_t)gra * ldb + koh + cw * 8;
            const __nv_bfloat16* sl = sh + K;
            uint32_t d = base + (uint32_t)(r * ROWP + cw * 8) * 2;
            cp16(d, sh, sz);
            cp16(d + A_SEC * 2, sl, sz);
        }
    };
    auto stageB_cp = [&](int c, uint32_t base) {
        int koh = c * 32;
        if (tid < 256) {
            int r = tid >> 2, cw = tid & 3;
            const __nv_bfloat16* sh = B + (size_t)(n0 + r) * ldb + koh + cw * 8;
            const __nv_bfloat16* sl = sh + K;
            uint32_t d = base + (uint32_t)(4 * A_SEC) + (uint32_t)(r * ROWP + cw * 8) * 2;
            cp16(d, sh, 16);
            cp16(d + B_SEC * 2, sl, 16);
        }
    };
    float4 av[4];
    auto loadA = [&](int c) {
        const float* A32 = (const float*)Aptr;
        int koh = c * 32;
#pragma unroll
        for (int i = 0; i < 4; ++i) {
            int idx = tid + 256 * i;
            int r = idx >> 3;
            int cc = (idx & 7) * 4;
            int gr = m0 + r;
            av[i] = (gr < M) ? __ldg((const float4*)(A32 + (size_t)gr * K + koh + cc))
                             : make_float4(0.f, 0.f, 0.f, 0.f);
        }
    };
    auto storeA = [&](int c, uint32_t baseOff) {
        __nv_bfloat16* sA = (__nv_bfloat16*)(smem + baseOff);
        int koh = c * 32;
#pragma unroll
        for (int i = 0; i < 4; ++i) {
            int idx = tid + 256 * i;
            int r = idx >> 3;
            int cc = (idx & 7) * 4;
            __nv_bfloat16 h[4], l[4];
#pragma unroll
            for (int j = 0; j < 4; ++j) {
                float u = (&av[i].x)[j];
                if (AMODE == 2) {
                    float2 p = __ldg(&g_bnp[prepOff + koh + cc + j]);
                    u = fmaf(u, p.x, p.y);
                    u = (u >= 0.f) ? u : NEG * u;
                }
                bsplit(u, h[j], l[j]);
            }
            __nv_bfloat162 h01, h23, l01, l23;
            h01.x = h[0]; h01.y = h[1]; h23.x = h[2]; h23.y = h[3];
            l01.x = l[0]; l01.y = l[1]; l23.x = l[2]; l23.y = l[3];
            uint2 hp, lp;
            hp.x = *(uint32_t*)&h01; hp.y = *(uint32_t*)&h23;
            lp.x = *(uint32_t*)&l01; lp.y = *(uint32_t*)&l23;
            *(uint2*)(sA + r * ROWP + cc) = hp;
            *(uint2*)(sA + A_SEC + r * ROWP + cc) = lp;
        }
    };

    float acc[2][4][4];
#pragma unroll
    for (int mi = 0; mi < 2; ++mi)
#pragma unroll
        for (int ni = 0; ni < 4; ++ni)
#pragma unroll
            for (int j = 0; j < 4; ++j) acc[mi][ni][j] = 0.f;

    if (AMODE == 0) {
        stageA_cp(0, uS);
    } else {
        loadA(0);
        storeA(0, 0);
    }
    stageB_cp(0, uS);
    CP_COMMIT();

    for (int c = 0; c < nch; ++c) {
        int p = c & 1;
        CP_WAIT0();
        __syncthreads();
        bool more = (c + 1 < nch);
        if (more) {
            uint32_t nbase = uS + (p ^ 1) * STAGE_BYTES;
            if (AMODE == 0) stageA_cp(c + 1, nbase);
            else            loadA(c + 1);
            stageB_cp(c + 1, nbase);
            CP_COMMIT();
        }
        mma_chunk(acc, off, uS + p * STAGE_BYTES);
        if (more && AMODE != 0)
            storeA(c + 1, (uint32_t)((p ^ 1) * STAGE_BYTES));
    }
    __syncthreads();

#pragma unroll
    for (int ni = 0; ni < 4; ++ni) {
        int colL = wn * 32 + ni * 8 + 2 * t;
        float s0 = 0.f, q0 = 0.f, s1 = 0.f, q1 = 0.f;
#pragma unroll
        for (int mi = 0; mi < 2; ++mi) {
            float* f = acc[mi][ni];
            int row = m0 + wm * 32 + mi * 16 + g;
            if (row < M) {
                C[(size_t)row * Nc + n0 + colL] = f[0];
                C[(size_t)row * Nc + n0 + colL + 1] = f[1];
                s0 += f[0]; q0 += f[0] * f[0];
                s1 += f[1]; q1 += f[1] * f[1];
            }
            if (row + 8 < M) {
                C[(size_t)(row + 8) * Nc + n0 + colL] = f[2];
                C[(size_t)(row + 8) * Nc + n0 + colL + 1] = f[3];
                s0 += f[2]; q0 += f[2] * f[2];
                s1 += f[3]; q1 += f[3] * f[3];
            }
        }
#pragma unroll
        for (int off2 = 4; off2 < 32; off2 <<= 1) {
            s0 += __shfl_xor_sync(0xffffffffu, s0, off2);
            q0 += __shfl_xor_sync(0xffffffffu, q0, off2);
            s1 += __shfl_xor_sync(0xffffffffu, s1, off2);
            q1 += __shfl_xor_sync(0xffffffffu, q1, off2);
        }
        if (g == 0) {
            atomicAdd(&red[colL], s0);
            atomicAdd(&red[64 + colL], q0);
            atomicAdd(&red[colL + 1], s1);
            atomicAdd(&red[64 + colL + 1], q1);
        }
    }
    __syncthreads();
    if (tid < 64) {
        atomicAdd(&g_stats[statOff + n0 + tid], (double)red[tid]);
        atomicAdd(&g_stats[statOff + Nc + n0 + tid], (double)red[64 + tid]);
    }
}

// ---------------- final: out = leaky(bn(u2)) + bn(usc), float4 ----------------
__global__ void final_kernel(float4* __restrict__ out, int n4) {
    int i = blockIdx.x * blockDim.x + threadIdx.x;
    if (i >= n4) return;
    int c4 = (i & 63) * 4;
    float4 a = __ldg((const float4*)g_u2 + i);
    float4 s = __ldg((const float4*)g_usc + i);
    float4 o;
#pragma unroll
    for (int j = 0; j < 4; ++j) {
        float2 p2 = __ldg(&g_bnp[128 + c4 + j]);
        float2 ps = __ldg(&g_bnp[384 + c4 + j]);
        float u = fmaf((&a.x)[j], p2.x, p2.y);
        u = (u >= 0.f) ? u : NEG * u;
        (&o.x)[j] = u + fmaf((&s.x)[j], ps.x, ps.y);
    }
    out[i] = o;
}

// ---------------- launch (multi-stream graph fork/join) ----------------
extern "C" void kernel_launch(void* const* d_in, const int* in_sizes, int n_in,
                              void* d_out, int out_size) {
    const float* pos    = (const float*)d_in[0];
    const float* x      = (const float*)d_in[1];
    const int*   e_ref  = (const int*)  d_in[2];
    const int*   e_qry  = (const int*)  d_in[3];
    const float* W1     = (const float*)d_in[4];
    const float* g1     = (const float*)d_in[5];
    const float* b1     = (const float*)d_in[6];
    const float* kp     = (const float*)d_in[7];
    const float* Wkp    = (const float*)d_in[8];
    const float* gkp    = (const float*)d_in[9];
    const float* bkp    = (const float*)d_in[10];
    const float* W2     = (const float*)d_in[11];
    const float* g2     = (const float*)d_in[12];
    const float* b2     = (const float*)d_in[13];
    const float* Wsc    = (const float*)d_in[14];
    const float* gsc    = (const float*)d_in[15];
    const float* bsc    = (const float*)d_in[16];
    float* out = (float*)d_out;

    const int M = NPTS;
    const int E = in_sizes[2];

    float *t_p, *u2_p, *usc_p;
    __nv_bfloat16 *Sb_p, *wkpb_p, *w1b_p, *w2b_p, *wscb_p;
    cudaGetSymbolAddress((void**)&t_p,    g_t);
    cudaGetSymbolAddress((void**)&u2_p,   g_u2);
    cudaGetSymbolAddress((void**)&usc_p,  g_usc);
    cudaGetSymbolAddress((void**)&Sb_p,   g_Sb);
    cudaGetSymbolAddress((void**)&w1b_p,  g_w1b);
    cudaGetSymbolAddress((void**)&wkpb_p, g_wkpb);
    cudaGetSymbolAddress((void**)&w2b_p,  g_w2b);
    cudaGetSymbolAddress((void**)&wscb_p, g_wscb);

    cudaFuncSetAttribute(gemm_uni<0>, cudaFuncAttributeMaxDynamicSharedMemorySize, GSMEM_BYTES);
    cudaFuncSetAttribute(gemm_uni<1>, cudaFuncAttributeMaxDynamicSharedMemorySize, GSMEM_BYTES);
    cudaFuncSetAttribute(gemm_uni<2>, cudaFuncAttributeMaxDynamicSharedMemorySize, GSMEM_BYTES);

    // one-time side stream + fork/join events (host handles; no device alloc)
    static cudaStream_t s2 = nullptr;
    static cudaEvent_t ev0 = nullptr, evW = nullptr, evS = nullptr, evU = nullptr;
    if (s2 == nullptr) {
        cudaStreamCreateWithFlags(&s2, cudaStreamNonBlocking);
        cudaEventCreateWithFlags(&ev0, cudaEventDisableTiming);
        cudaEventCreateWithFlags(&evW, cudaEventDisableTiming);
        cudaEventCreateWithFlags(&evS, cudaEventDisableTiming);
        cudaEventCreateWithFlags(&evU, cudaEventDisableTiming);
    }

    const int MB = (M + 127) / 128;
    int n4_256 = M * DOUT / 4;

    // ---- default stream: start of critical chain ----
    zero_kernel<<<(NPTS + 255) / 256, 256>>>();
    cudaEventRecord(ev0, 0);                       // fork point (after zero)
    wsplit_all<<<(WSPLIT_TOTAL + 255) / 256, 256>>>(W1, Wkp, W2, Wsc);
    cudaEventRecord(evW, 0);                       // weights ready

    // ---- side stream: scatter, then usc GEMM ----
    cudaStreamWaitEvent(s2, ev0, 0);
    scatter_kernel<<<(E + 255) / 256, 256, 0, s2>>>(e_ref, e_qry, E);
    cudaEventRecord(evS, s2);                      // binning done
    cudaStreamWaitEvent(s2, evW, 0);
    gemm_uni<1><<<dim3(MB, 4), 256, GSMEM_BYTES, s2>>>(x, wscb_p, usc_p, M, DIN, DOUT, 768, 0);
    cudaEventRecord(evU, s2);                      // usc done

    // ---- default stream: critical chain continues ----
    gemm_uni<1><<<dim3(MB, 1), 256, GSMEM_BYTES>>>(x, w1b_p, t_p, M, DIN, D2, 0, 0);
    bn_prep<<<1, 64>>>(0, D2, g1, b1, 0, M);
    cudaStreamWaitEvent(0, evS, 0);                // need binning before sbuild
    sbuild_kernel<<<(M + 7) / 8, 256>>>(pos, kp);
    gemm_uni<0><<<dim3(MB, 1), 256, GSMEM_BYTES>>>(Sb_p, wkpb_p, t_p, M, KPTS * D2, D2, 128, 0);
    bn_prep<<<1, 64>>>(128, D2, gkp, bkp, 64, M);
    gemm_uni<2><<<dim3(MB, 4), 256, GSMEM_BYTES>>>(t_p, w2b_p, u2_p, M, D2, DOUT, 256, 64);
    cudaStreamWaitEvent(0, evU, 0);                // join usc branch
    bn_prep2<<<1, 512>>>(g2, b2, gsc, bsc, M);
    final_kernel<<<(n4_256 + 255) / 256, 256>>>((float4*)out, n4_256);
}